// round 7
// baseline (speedup 1.0000x reference)
#include <cuda_runtime.h>
#include <math.h>
#include <cstdint>

// Problem constants (fixed by dataset; k_input=2048, k_process=1024 always)
#define BB   8
#define SS   2048
#define DM   1024
#define NIN  4096
#define NP   2048
#define DR   256
#define KI   2048
#define KP   1024

// ---------------- scratch (static __device__ globals; no allocation) ----------------
__device__ float g_gctx [BB * DM];
__device__ float g_h    [BB * 512];
__device__ float g_hn   [BB * 512];
__device__ float g_query[BB * DR];
__device__ float g_logits[BB * NIN];
__device__ float g_scores[BB * NP];
__device__ int   g_iidx [BB * KI];
__device__ int   g_pidx [BB * KP];
__device__ float g_selin[(size_t)BB * SS * KI];   // 134 MB
__device__ float g_wsel [(size_t)BB * NP * KI];   // 134 MB
__device__ float g_pa   [(size_t)BB * SS * NP];   // 134 MB
__device__ float g_pasel[(size_t)BB * SS * KP];   //  67 MB
__device__ float g_poT  [(size_t)BB * DM * KP];   //  67 MB

__device__ __forceinline__ float geluf(float v) {
    return 0.5f * v * (1.0f + erff(v * 0.70710678118654752440f));
}

__device__ __forceinline__ uint32_t smem_u32(const void* p) {
    uint32_t a;
    asm("{ .reg .u64 t; cvta.to.shared.u64 t, %1; cvt.u32.u64 %0, t; }" : "=r"(a) : "l"(p));
    return a;
}

__device__ __forceinline__ void cp16(uint32_t dst, const void* src) {
    asm volatile("cp.async.cg.shared.global [%0], [%1], 16;" :: "r"(dst), "l"(src) : "memory");
}

__device__ __forceinline__ uint32_t tf32_hi(float x) {
    return __float_as_uint(x) & 0xFFFFE000u;
}
// lo term: raw fp32 bits of (x - hi); mma.tf32 HW truncates operands to tf32 anyway,
// so an explicit mask here is redundant (identical numerics, fewer ALU ops).
__device__ __forceinline__ uint32_t tf32_lo(float x, uint32_t h) {
    return __float_as_uint(x - __uint_as_float(h));
}

__device__ __forceinline__ void mma8(float* c,
    uint32_t a0, uint32_t a1, uint32_t a2, uint32_t a3, uint32_t b0, uint32_t b1) {
    asm volatile(
        "mma.sync.aligned.m16n8k8.row.col.f32.tf32.tf32.f32 "
        "{%0,%1,%2,%3}, {%4,%5,%6,%7}, {%8,%9}, {%0,%1,%2,%3};"
        : "+f"(c[0]), "+f"(c[1]), "+f"(c[2]), "+f"(c[3])
        : "r"(a0), "r"(a1), "r"(a2), "r"(a3), "r"(b0), "r"(b1));
}

// smem: 4 stages, each = A[128*36] + B[128*36] floats (pad 36 => conflict-free frags)
#define PADW 36
#define HALF_FLOATS (128 * PADW)            // one operand plane
#define STG_FLOATS  (2 * HALF_FLOATS)       // A plane + B plane per stage
#define NSTAGE 4
#define SMEM_BYTES (NSTAGE * STG_FLOATS * 4)   // 147456

// ---------------- 3xTF32 mma.sync GEMM: C = act(A * B^T) ----------------
// A [M x K] row-major K-contig, B [N x K] row-major K-contig (optional row gather).
// CTA tile 128x128, BK=32, 256 threads (8 warps, 4M x 2N), warp tile 32x64.
// 4-stage cp.async pipeline, one barrier per iteration.
template<bool DOGELU, bool GATHERB>
__global__ void __launch_bounds__(256) mma_nt(
    const float* __restrict__ A, const float* __restrict__ Bm, float* __restrict__ Cm,
    const int* __restrict__ gidx, int Ncols, int K,
    size_t sA, size_t sB, size_t sC, int sG)
{
    extern __shared__ __align__(16) float smem[];
    const int tid = threadIdx.x, wid = tid >> 5, lane = tid & 31;
    const int lq = lane >> 2, lr = lane & 3;
    const int wm = wid & 3, wn = wid >> 2;
    const int zb = blockIdx.z;
    A  += (size_t)zb * sA;
    Bm += (size_t)zb * sB;
    Cm += (size_t)zb * sC;
    const int m0 = blockIdx.y * 128, n0 = blockIdx.x * 128;

    const uint32_t sbA = smem_u32(smem);

    // loader: 4 chunks of 16B each for A and B per thread per stage
    const float* aSrc[4]; const float* bSrc[4]; uint32_t dOff[4];
    #pragma unroll
    for (int c = 0; c < 4; c++) {
        int id = tid + 256 * c;
        int r = id >> 3, kc = (id & 7) * 4;
        aSrc[c] = A + (size_t)(m0 + r) * K + kc;
        int br = n0 + r;
        int bs_ = GATHERB ? gidx[(size_t)zb * sG + br] : br;
        bSrc[c] = Bm + (size_t)bs_ * K + kc;
        dOff[c] = (uint32_t)(r * PADW + kc) * 4;
    }

    float acc[2][8][4];
    #pragma unroll
    for (int mf = 0; mf < 2; mf++)
        #pragma unroll
        for (int nf = 0; nf < 8; nf++)
            #pragma unroll
            for (int q = 0; q < 4; q++) acc[mf][nf][q] = 0.f;

    const int T = K >> 5;

    // prologue: stages 0..2
    #pragma unroll
    for (int s = 0; s < NSTAGE - 1; s++) {
        uint32_t so = (uint32_t)(s * STG_FLOATS) * 4;
        int kb = s * 32;
        if (s < T) {
            #pragma unroll
            for (int c = 0; c < 4; c++) {
                cp16(sbA + so + dOff[c], aSrc[c] + kb);
                cp16(sbA + so + HALF_FLOATS * 4 + dOff[c], bSrc[c] + kb);
            }
        }
        asm volatile("cp.async.commit_group;" ::: "memory");
    }

    for (int i = 0; i < T; i++) {
        asm volatile("cp.async.wait_group %0;" :: "n"(NSTAGE - 2) : "memory");
        __syncthreads();

        // prefetch stage i+3 into buffer (i+3)&3  (empty commit at tail keeps counting uniform)
        {
            int ps = i + NSTAGE - 1;
            if (ps < T) {
                uint32_t so = (uint32_t)((ps & (NSTAGE - 1)) * STG_FLOATS) * 4;
                int kb = ps * 32;
                #pragma unroll
                for (int c = 0; c < 4; c++) {
                    cp16(sbA + so + dOff[c], aSrc[c] + kb);
                    cp16(sbA + so + HALF_FLOATS * 4 + dOff[c], bSrc[c] + kb);
                }
            }
            asm volatile("cp.async.commit_group;" ::: "memory");
        }

        const float* Asf = smem + (i & (NSTAGE - 1)) * STG_FLOATS + (wm * 32) * PADW;
        const float* Bsf = smem + (i & (NSTAGE - 1)) * STG_FLOATS + HALF_FLOATS + (wn * 64) * PADW;

        #pragma unroll
        for (int ks = 0; ks < 4; ks++) {
            const int c0 = ks * 8 + lr;
            uint32_t ah[2][4], al[2][4];
            #pragma unroll
            for (int mf = 0; mf < 2; mf++) {
                int rb = mf * 16 + lq;
                float a0 = Asf[rb * PADW + c0];
                float a1 = Asf[(rb + 8) * PADW + c0];
                float a2 = Asf[rb * PADW + c0 + 4];
                float a3 = Asf[(rb + 8) * PADW + c0 + 4];
                ah[mf][0] = tf32_hi(a0); al[mf][0] = tf32_lo(a0, ah[mf][0]);
                ah[mf][1] = tf32_hi(a1); al[mf][1] = tf32_lo(a1, ah[mf][1]);
                ah[mf][2] = tf32_hi(a2); al[mf][2] = tf32_lo(a2, ah[mf][2]);
                ah[mf][3] = tf32_hi(a3); al[mf][3] = tf32_lo(a3, ah[mf][3]);
            }
            uint32_t bh[8][2], bl[8][2];
            #pragma unroll
            for (int nf = 0; nf < 8; nf++) {
                int nr = nf * 8 + lq;
                float b0 = Bsf[nr * PADW + c0];
                float b1 = Bsf[nr * PADW + c0 + 4];
                bh[nf][0] = tf32_hi(b0); bl[nf][0] = tf32_lo(b0, bh[nf][0]);
                bh[nf][1] = tf32_hi(b1); bl[nf][1] = tf32_lo(b1, bh[nf][1]);
            }
            #pragma unroll
            for (int mf = 0; mf < 2; mf++)
                #pragma unroll
                for (int nf = 0; nf < 8; nf++) {
                    mma8(acc[mf][nf], ah[mf][0], ah[mf][1], ah[mf][2], ah[mf][3], bh[nf][0], bh[nf][1]);
                    mma8(acc[mf][nf], al[mf][0], al[mf][1], al[mf][2], al[mf][3], bh[nf][0], bh[nf][1]);
                    mma8(acc[mf][nf], ah[mf][0], ah[mf][1], ah[mf][2], ah[mf][3], bl[nf][0], bl[nf][1]);
                }
        }
    }

    // epilogue
    #pragma unroll
    for (int mf = 0; mf < 2; mf++) {
        int row0 = m0 + wm * 32 + mf * 16 + lq;
        #pragma unroll
        for (int nf = 0; nf < 8; nf++) {
            int col = n0 + wn * 64 + nf * 8 + 2 * lr;
            float2 v0, v1;
            v0.x = acc[mf][nf][0]; v0.y = acc[mf][nf][1];
            v1.x = acc[mf][nf][2]; v1.y = acc[mf][nf][3];
            if (DOGELU) {
                v0.x = geluf(v0.x); v0.y = geluf(v0.y);
                v1.x = geluf(v1.x); v1.y = geluf(v1.y);
            }
            *(float2*)(Cm + (size_t)row0 * Ncols + col) = v0;
            *(float2*)(Cm + (size_t)(row0 + 8) * Ncols + col) = v1;
        }
    }
}

// ---------------- router ----------------
__global__ void k_rowmax(const float* __restrict__ x) {
    int t = blockIdx.x * blockDim.x + threadIdx.x;
    int b = t >> 10, d = t & (DM - 1);
    const float* p = x + (size_t)b * SS * DM + d;
    float m = -INFINITY;
    #pragma unroll 8
    for (int s = 0; s < SS; s++) m = fmaxf(m, p[(size_t)s * DM]);
    g_gctx[t] = m;
}

__global__ void k_mlp1(const float* __restrict__ W1, const float* __restrict__ b1) {
    int gw = (blockIdx.x * blockDim.x + threadIdx.x) >> 5;
    int lane = threadIdx.x & 31;
    int b = gw >> 9, o = gw & 511;
    const float* g = g_gctx + b * DM;
    const float* w = W1 + (size_t)o * DM;
    float s = 0.f;
    for (int k = lane; k < DM; k += 32) s += g[k] * w[k];
    #pragma unroll
    for (int off = 16; off; off >>= 1) s += __shfl_xor_sync(0xffffffffu, s, off);
    if (lane == 0) g_h[gw] = geluf(s + b1[o]);
}

__global__ void k_ln(const float* __restrict__ lng, const float* __restrict__ lnb) {
    __shared__ float red[512];
    int b = blockIdx.x, tid = threadIdx.x;
    float v = g_h[b * 512 + tid];
    red[tid] = v;
    for (int s = 256; s; s >>= 1) { __syncthreads(); if (tid < s) red[tid] += red[tid + s]; }
    __syncthreads();
    float mu = red[0] * (1.f / 512.f);
    __syncthreads();
    float dv = v - mu;
    red[tid] = dv * dv;
    for (int s = 256; s; s >>= 1) { __syncthreads(); if (tid < s) red[tid] += red[tid + s]; }
    __syncthreads();
    float var = red[0] * (1.f / 512.f);
    g_hn[b * 512 + tid] = dv * rsqrtf(var + 1e-5f) * lng[tid] + lnb[tid];
}

__global__ void k_mlp2(const float* __restrict__ W2, const float* __restrict__ b2) {
    int gw = (blockIdx.x * blockDim.x + threadIdx.x) >> 5;
    int lane = threadIdx.x & 31;
    int b = gw >> 8, o = gw & 255;
    const float* hrow = g_hn + b * 512;
    const float* w = W2 + (size_t)o * 512;
    float s = 0.f;
    for (int k = lane; k < 512; k += 32) s += hrow[k] * w[k];
    #pragma unroll
    for (int off = 16; off; off >>= 1) s += __shfl_xor_sync(0xffffffffu, s, off);
    if (lane == 0) g_query[gw] = s + b2[o];
}

__global__ void k_logits(const float* __restrict__ nk) {
    int gw = (blockIdx.x * blockDim.x + threadIdx.x) >> 5;
    int lane = threadIdx.x & 31;
    int b = gw >> 12, n = gw & (NIN - 1);
    const float* q = g_query + b * DR;
    const float* w = nk + (size_t)n * DR;
    float s = 0.f;
    #pragma unroll
    for (int k = lane; k < DR; k += 32) s += q[k] * w[k];
    #pragma unroll
    for (int off = 16; off; off >>= 1) s += __shfl_xor_sync(0xffffffffu, s, off);
    if (lane == 0) g_logits[gw] = s * 0.0625f;
}

// ---------------- exact top-k via bitonic sort; index set emitted sorted ascending ----------------
__global__ void k_topk(const float* __restrict__ vals, int N, int Ksel, int* __restrict__ outIdx) {
    __shared__ float sv[4096];
    __shared__ int   si[4096];
    int b = blockIdx.x, tid = threadIdx.x, bs = blockDim.x;
    for (int i = tid; i < N; i += bs) { sv[i] = vals[b * N + i]; si[i] = i; }
    for (int k = 2; k <= N; k <<= 1) {
        for (int j = k >> 1; j > 0; j >>= 1) {
            __syncthreads();
            for (int i = tid; i < N; i += bs) {
                int l = i ^ j;
                if (l > i) {
                    float vi = sv[i], vl = sv[l];
                    int ii = si[i], il = si[l];
                    bool lFirst = (vl > vi) || (vl == vi && il < ii);
                    bool sw = ((i & k) == 0) ? lFirst : !lFirst;
                    if (sw) { sv[i] = vl; sv[l] = vi; si[i] = il; si[l] = ii; }
                }
            }
        }
    }
    __syncthreads();
    int* sel = (int*)sv;
    for (int i = tid; i < Ksel; i += bs) sel[i] = si[i];
    for (int k = 2; k <= Ksel; k <<= 1) {
        for (int j = k >> 1; j > 0; j >>= 1) {
            __syncthreads();
            for (int i = tid; i < Ksel; i += bs) {
                int l = i ^ j;
                if (l > i) {
                    int a = sel[i], c = sel[l];
                    bool sw = ((i & k) == 0) ? (c < a) : (c > a);
                    if (sw) { sel[i] = c; sel[l] = a; }
                }
            }
        }
    }
    __syncthreads();
    for (int i = tid; i < Ksel; i += bs) outIdx[b * Ksel + i] = sel[i];
}

// ---------------- gathers / reductions ----------------
__global__ void k_gather_wsel(const float* __restrict__ pw) {
    size_t t = (size_t)blockIdx.x * blockDim.x + threadIdx.x;
    int j = (int)(t & (KI - 1));
    size_t bp = t >> 11;
    int p = (int)(bp & (NP - 1));
    int b = (int)(bp >> 11);
    g_wsel[t] = pw[(size_t)p * NIN + g_iidx[b * KI + j]];
}

__global__ void k_scores() {
    int t = blockIdx.x * blockDim.x + threadIdx.x;
    int b = t >> 11, p = t & (NP - 1);
    const float* q = g_pa + (size_t)b * SS * NP + p;
    float s = 0.f;
    #pragma unroll 4
    for (int i = 0; i < SS; i++) s += q[(size_t)i * NP];
    g_scores[t] = s * (1.f / (float)SS);
}

__global__ void k_gather_pasel() {
    size_t t = (size_t)blockIdx.x * blockDim.x + threadIdx.x;
    int q = (int)(t & (KP - 1));
    size_t bs_ = t >> 10;
    int s = (int)(bs_ & (SS - 1));
    int b = (int)(bs_ >> 11);
    g_pasel[t] = g_pa[((size_t)(b * SS + s)) * NP + g_pidx[b * KP + q]];
}

// poT[b][d][q] = po[pidx[b][q]][d]   (32x32 smem transpose, coalesced both sides)
__global__ void k_build_poT(const float* __restrict__ po) {
    __shared__ float t[32][33];
    int b = blockIdx.z;
    int q0 = blockIdx.x * 32, d0 = blockIdx.y * 32;
    int tx = threadIdx.x, ty = threadIdx.y;
    for (int yy = ty; yy < 32; yy += 8) {
        int p = g_pidx[b * KP + q0 + yy];
        t[yy][tx] = po[(size_t)p * DM + d0 + tx];
    }
    __syncthreads();
    for (int yy = ty; yy < 32; yy += 8)
        g_poT[((size_t)b * DM + d0 + yy) * KP + q0 + tx] = t[tx][yy];
}

// ---------------- launch ----------------
extern "C" void kernel_launch(void* const* d_in, const int* in_sizes, int n_in,
                              void* d_out, int out_size) {
    const float* x   = (const float*)d_in[0];
    const float* W1  = (const float*)d_in[3];
    const float* b1  = (const float*)d_in[4];
    const float* lng = (const float*)d_in[5];
    const float* lnb = (const float*)d_in[6];
    const float* W2  = (const float*)d_in[7];
    const float* b2  = (const float*)d_in[8];
    const float* nk  = (const float*)d_in[9];
    const float* ip  = (const float*)d_in[10];
    const float* pw  = (const float*)d_in[11];
    const float* po  = (const float*)d_in[12];
    float* out = (float*)d_out;

    float *p_logits, *p_scores, *p_selin, *p_wsel, *p_pa, *p_pasel, *p_poT;
    int *p_iidx, *p_pidx;
    cudaGetSymbolAddress((void**)&p_logits, g_logits);
    cudaGetSymbolAddress((void**)&p_scores, g_scores);
    cudaGetSymbolAddress((void**)&p_selin,  g_selin);
    cudaGetSymbolAddress((void**)&p_wsel,   g_wsel);
    cudaGetSymbolAddress((void**)&p_pa,     g_pa);
    cudaGetSymbolAddress((void**)&p_pasel,  g_pasel);
    cudaGetSymbolAddress((void**)&p_poT,    g_poT);
    cudaGetSymbolAddress((void**)&p_iidx,   g_iidx);
    cudaGetSymbolAddress((void**)&p_pidx,   g_pidx);

    cudaFuncSetAttribute(mma_nt<true,  true >, cudaFuncAttributeMaxDynamicSharedMemorySize, SMEM_BYTES);
    cudaFuncSetAttribute(mma_nt<true,  false>, cudaFuncAttributeMaxDynamicSharedMemorySize, SMEM_BYTES);
    cudaFuncSetAttribute(mma_nt<false, false>, cudaFuncAttributeMaxDynamicSharedMemorySize, SMEM_BYTES);

    // router (fp32 exact)
    k_rowmax<<<BB * DM / 256, 256>>>(x);
    k_mlp1<<<BB * 512 * 32 / 256, 256>>>(W1, b1);
    k_ln<<<BB, 512>>>(lng, lnb);
    k_mlp2<<<BB * 256 * 32 / 256, 256>>>(W2, b2);
    k_logits<<<BB * NIN * 32 / 256, 256>>>(nk);
    k_topk<<<BB, 1024>>>(p_logits, NIN, KI, p_iidx);

    // stage 1: sel_in = gelu(x @ gathered_patterns^T)   [3xTF32 mma.sync]
    k_gather_wsel<<<(int)((size_t)BB * NP * KI / 256), 256>>>(pw);
    mma_nt<true, true><<<dim3(KI / 128, SS / 128, BB), 256, SMEM_BYTES>>>(
        x, ip, p_selin, p_iidx, KI, DM,
        (size_t)SS * DM, 0, (size_t)SS * KI, KI);

    // stage 2: pa = gelu(sel_in @ W_sel^T)   [3xTF32 mma.sync]
    mma_nt<true, false><<<dim3(NP / 128, SS / 128, BB), 256, SMEM_BYTES>>>(
        p_selin, p_wsel, p_pa, nullptr, NP, KI,
        (size_t)SS * KI, (size_t)NP * KI, (size_t)SS * NP, 0);

    // process selection
    k_scores<<<BB * NP / 256, 256>>>();
    k_topk<<<BB, 1024>>>(p_scores, NP, KP, p_pidx);
    k_gather_pasel<<<(int)((size_t)BB * SS * KP / 256), 256>>>();
    k_build_poT<<<dim3(KP / 32, DM / 32, BB), dim3(32, 8)>>>(po);

    // final: out = pa_sel @ poT^T   [3xTF32 mma.sync]
    mma_nt<false, false><<<dim3(DM / 128, SS / 128, BB), 256, SMEM_BYTES>>>(
        p_pasel, p_poT, out, nullptr, DM, KP,
        (size_t)SS * KP, (size_t)DM * KP, (size_t)SS * DM, 0);
}

// round 9
// speedup vs baseline: 1.2930x; 1.2930x over previous
#include <cuda_runtime.h>
#include <cuda_fp16.h>
#include <math.h>
#include <cstdint>

// Problem constants (fixed by dataset; k_input=2048, k_process=1024 always)
#define BB   8
#define SS   2048
#define DM   1024
#define NIN  4096
#define NP   2048
#define DR   256
#define KI   2048
#define KP   1024

// B-operand scaling (exact power of 2): keeps fp16 lo-terms out of subnormal range
#define BSCALE   32.0f
#define BINV     0.03125f

// ---------------- scratch (static __device__ globals; no allocation) ----------------
__device__ float g_gctx [BB * DM];
__device__ float g_query[BB * DR];
__device__ float g_logits[BB * NIN];
__device__ float g_scores[BB * NP];
__device__ int   g_iidx [BB * KI];
__device__ int   g_pidx [BB * KP];
__device__ float g_selin[(size_t)BB * SS * KI];   // 134 MB
__device__ float g_wsel [(size_t)BB * NP * KI];   // 134 MB
__device__ float g_pa   [(size_t)BB * SS * NP];   // 134 MB
__device__ float g_pasel[(size_t)BB * SS * KP];   //  67 MB
__device__ float g_poT  [(size_t)BB * DM * KP];   //  67 MB

__device__ __forceinline__ float geluf(float v) {
    return 0.5f * v * (1.0f + erff(v * 0.70710678118654752440f));
}

__device__ __forceinline__ void cp16(uint32_t dst, const void* src) {
    asm volatile("cp.async.cg.shared.global [%0], [%1], 16;" :: "r"(dst), "l"(src) : "memory");
}
__device__ __forceinline__ uint32_t smem_u32(const void* p) {
    uint32_t a;
    asm("{ .reg .u64 t; cvta.to.shared.u64 t, %1; cvt.u32.u64 %0, t; }" : "=r"(a) : "l"(p));
    return a;
}

// Markidis split of a float2 into (hi, lo) packed half2 pairs
__device__ __forceinline__ void split2(float x, float y, uint32_t& h, uint32_t& l) {
    __half2 hh = __floats2half2_rn(x, y);
    float2 hf = __half22float2(hh);
    __half2 ll = __floats2half2_rn(x - hf.x, y - hf.y);
    h = *reinterpret_cast<uint32_t*>(&hh);
    l = *reinterpret_cast<uint32_t*>(&ll);
}

__device__ __forceinline__ void mma16(float* c, const uint32_t* a, const uint32_t* b) {
    asm volatile(
        "mma.sync.aligned.m16n8k16.row.col.f32.f16.f16.f32 "
        "{%0,%1,%2,%3}, {%4,%5,%6,%7}, {%8,%9}, {%0,%1,%2,%3};"
        : "+f"(c[0]), "+f"(c[1]), "+f"(c[2]), "+f"(c[3])
        : "r"(a[0]), "r"(a[1]), "r"(a[2]), "r"(a[3]), "r"(b[0]), "r"(b[1]));
}

// smem: NSTAGE stages, each = A[128*PADW] + B[128*PADW] floats.
// PADW=40: float2 fragment loads hit words (8*lq + 2*lr) mod 32 -> phase-conflict-free.
#define PADW 40
#define HALF_FLOATS (128 * PADW)
#define STG_FLOATS  (2 * HALF_FLOATS)
#define NSTAGE 3
#define SMEM_BYTES (NSTAGE * STG_FLOATS * 4)   // 122880

// ---------------- 3xFP16 mma.sync GEMM: C = act(A * (B*BSCALE)^T) * BINV ----------------
// A [M x K] row-major K-contig, B [N x K] row-major K-contig (optional row gather).
// CTA tile 128x128, BK=32, 256 threads (8 warps, 4M x 2N), warp tile 32x64.
template<bool DOGELU, bool GATHERB>
__global__ void __launch_bounds__(256) mma_nt(
    const float* __restrict__ A, const float* __restrict__ Bm, float* __restrict__ Cm,
    const int* __restrict__ gidx, int Ncols, int K,
    size_t sA, size_t sB, size_t sC, int sG)
{
    extern __shared__ __align__(16) float smem[];
    const int tid = threadIdx.x, wid = tid >> 5, lane = tid & 31;
    const int lq = lane >> 2, lr = lane & 3;
    const int wm = wid & 3, wn = wid >> 2;
    const int zb = blockIdx.z;
    A  += (size_t)zb * sA;
    Bm += (size_t)zb * sB;
    Cm += (size_t)zb * sC;
    const int m0 = blockIdx.y * 128, n0 = blockIdx.x * 128;

    const uint32_t sbA = smem_u32(smem);

    // loader: 4 chunks of 16B each for A and B planes per thread per stage
    const float* aSrc[4]; const float* bSrc[4]; uint32_t dOff[4];
    #pragma unroll
    for (int c = 0; c < 4; c++) {
        int id = tid + 256 * c;
        int r = id >> 3, kc = (id & 7) * 4;
        aSrc[c] = A + (size_t)(m0 + r) * K + kc;
        int br = n0 + r;
        int bs_ = GATHERB ? gidx[(size_t)zb * sG + br] : br;
        bSrc[c] = Bm + (size_t)bs_ * K + kc;
        dOff[c] = (uint32_t)(r * PADW + kc) * 4;
    }

    float acc[2][8][4];
    #pragma unroll
    for (int mf = 0; mf < 2; mf++)
        #pragma unroll
        for (int nf = 0; nf < 8; nf++)
            #pragma unroll
            for (int q = 0; q < 4; q++) acc[mf][nf][q] = 0.f;

    const int T = K >> 5;

    // prologue: stages 0..NSTAGE-2
    #pragma unroll
    for (int s = 0; s < NSTAGE - 1; s++) {
        uint32_t so = (uint32_t)(s * STG_FLOATS) * 4;
        int kb = s * 32;
        if (s < T) {
            #pragma unroll
            for (int c = 0; c < 4; c++) {
                cp16(sbA + so + dOff[c], aSrc[c] + kb);
                cp16(sbA + so + HALF_FLOATS * 4 + dOff[c], bSrc[c] + kb);
            }
        }
        asm volatile("cp.async.commit_group;" ::: "memory");
    }

    int stg = 0;
    for (int i = 0; i < T; i++) {
        asm volatile("cp.async.wait_group %0;" :: "n"(NSTAGE - 2) : "memory");
        __syncthreads();

        // prefetch stage i+NSTAGE-1 (uniform empty commit at tail)
        {
            int ps = i + NSTAGE - 1;
            int pstg = stg + NSTAGE - 1; if (pstg >= NSTAGE) pstg -= NSTAGE;
            if (ps < T) {
                uint32_t so = (uint32_t)(pstg * STG_FLOATS) * 4;
                int kb = ps * 32;
                #pragma unroll
                for (int c = 0; c < 4; c++) {
                    cp16(sbA + so + dOff[c], aSrc[c] + kb);
                    cp16(sbA + so + HALF_FLOATS * 4 + dOff[c], bSrc[c] + kb);
                }
            }
            asm volatile("cp.async.commit_group;" ::: "memory");
        }

        const float* Asf = smem + stg * STG_FLOATS + (wm * 32) * PADW;
        const float* Bsf = smem + stg * STG_FLOATS + HALF_FLOATS + (wn * 64) * PADW;

        #pragma unroll
        for (int ks = 0; ks < 2; ks++) {
            const int c0 = ks * 16 + 2 * lr;
            uint32_t ah[2][4], al[2][4];
            #pragma unroll
            for (int mf = 0; mf < 2; mf++) {
                int rb = mf * 16 + lq;
                float2 v0 = *(const float2*)&Asf[rb * PADW + c0];
                float2 v1 = *(const float2*)&Asf[(rb + 8) * PADW + c0];
                float2 v2 = *(const float2*)&Asf[rb * PADW + c0 + 8];
                float2 v3 = *(const float2*)&Asf[(rb + 8) * PADW + c0 + 8];
                split2(v0.x, v0.y, ah[mf][0], al[mf][0]);
                split2(v1.x, v1.y, ah[mf][1], al[mf][1]);
                split2(v2.x, v2.y, ah[mf][2], al[mf][2]);
                split2(v3.x, v3.y, ah[mf][3], al[mf][3]);
            }
            uint32_t bh[8][2], bl[8][2];
            #pragma unroll
            for (int nf = 0; nf < 8; nf++) {
                int nr = nf * 8 + lq;
                float2 u0 = *(const float2*)&Bsf[nr * PADW + c0];
                float2 u1 = *(const float2*)&Bsf[nr * PADW + c0 + 8];
                split2(u0.x * BSCALE, u0.y * BSCALE, bh[nf][0], bl[nf][0]);
                split2(u1.x * BSCALE, u1.y * BSCALE, bh[nf][1], bl[nf][1]);
            }
            #pragma unroll
            for (int mf = 0; mf < 2; mf++)
                #pragma unroll
                for (int nf = 0; nf < 8; nf++) {
                    mma16(acc[mf][nf], ah[mf], bh[nf]);
                    mma16(acc[mf][nf], al[mf], bh[nf]);
                    mma16(acc[mf][nf], ah[mf], bl[nf]);
                }
        }
        if (++stg == NSTAGE) stg = 0;
    }

    // epilogue (unscale, optional GELU)
    #pragma unroll
    for (int mf = 0; mf < 2; mf++) {
        int row0 = m0 + wm * 32 + mf * 16 + lq;
        #pragma unroll
        for (int nf = 0; nf < 8; nf++) {
            int col = n0 + wn * 64 + nf * 8 + 2 * lr;
            float2 v0, v1;
            v0.x = acc[mf][nf][0] * BINV; v0.y = acc[mf][nf][1] * BINV;
            v1.x = acc[mf][nf][2] * BINV; v1.y = acc[mf][nf][3] * BINV;
            if (DOGELU) {
                v0.x = geluf(v0.x); v0.y = geluf(v0.y);
                v1.x = geluf(v1.x); v1.y = geluf(v1.y);
            }
            *(float2*)(Cm + (size_t)row0 * Ncols + col) = v0;
            *(float2*)(Cm + (size_t)(row0 + 8) * Ncols + col) = v1;
        }
    }
}

// ---------------- router ----------------
__global__ void k_rowmax(const float* __restrict__ x) {
    int t = blockIdx.x * blockDim.x + threadIdx.x;
    int b = t >> 10, d = t & (DM - 1);
    const float* p = x + (size_t)b * SS * DM + d;
    float m = -INFINITY;
    #pragma unroll 8
    for (int s = 0; s < SS; s++) m = fmaxf(m, p[(size_t)s * DM]);
    g_gctx[t] = m;
}

// fused: mlp1 -> gelu -> LN -> mlp2 -> logits   (one block per batch, 512 thr)
__global__ void __launch_bounds__(512) k_router(
    const float* __restrict__ W1, const float* __restrict__ b1,
    const float* __restrict__ lng, const float* __restrict__ lnb,
    const float* __restrict__ W2, const float* __restrict__ b2,
    const float* __restrict__ nk)
{
    int b = blockIdx.x, tid = threadIdx.x, wid = tid >> 5, lane = tid & 31;
    __shared__ float sg[1024];
    __shared__ float sh[512];
    __shared__ float red[512];
    __shared__ float sq[256];
    sg[tid] = g_gctx[b * 1024 + tid];
    sg[tid + 512] = g_gctx[b * 1024 + 512 + tid];
    __syncthreads();
    // mlp1: 16 warps x 32 outputs (warp-dot, coalesced W1 rows)
    for (int oo = 0; oo < 32; oo++) {
        int o = wid * 32 + oo;
        const float* w = W1 + (size_t)o * 1024;
        float s = 0.f;
        for (int k = lane; k < 1024; k += 32) s += sg[k] * w[k];
        #pragma unroll
        for (int off = 16; off; off >>= 1) s += __shfl_xor_sync(0xffffffffu, s, off);
        if (lane == 0) sh[o] = geluf(s + b1[o]);
    }
    __syncthreads();
    // LayerNorm over 512
    float v = sh[tid];
    red[tid] = v;
    for (int s = 256; s; s >>= 1) { __syncthreads(); if (tid < s) red[tid] += red[tid + s]; }
    __syncthreads();
    float mu = red[0] * (1.f / 512.f);
    __syncthreads();
    float dv = v - mu;
    red[tid] = dv * dv;
    for (int s = 256; s; s >>= 1) { __syncthreads(); if (tid < s) red[tid] += red[tid + s]; }
    __syncthreads();
    float var = red[0] * (1.f / 512.f);
    __syncthreads();
    sh[tid] = dv * rsqrtf(var + 1e-5f) * lng[tid] + lnb[tid];
    __syncthreads();
    // mlp2: 16 warps x 16 outputs
    for (int oo = 0; oo < 16; oo++) {
        int o = wid * 16 + oo;
        const float* w = W2 + (size_t)o * 512;
        float s = 0.f;
        for (int k = lane; k < 512; k += 32) s += sh[k] * w[k];
        #pragma unroll
        for (int off = 16; off; off >>= 1) s += __shfl_xor_sync(0xffffffffu, s, off);
        if (lane == 0) sq[o] = s + b2[o];
    }
    __syncthreads();
    // logits: 16 warps x 256 outputs, dot-256
    for (int oo = 0; oo < 256; oo++) {
        int n = wid * 256 + oo;
        const float* w = nk + (size_t)n * 256;
        float s = 0.f;
        #pragma unroll
        for (int k = lane; k < 256; k += 32) s += sq[k] * w[k];
        #pragma unroll
        for (int off = 16; off; off >>= 1) s += __shfl_xor_sync(0xffffffffu, s, off);
        if (lane == 0) g_logits[b * 4096 + n] = s * 0.0625f;
    }
}

// ---------------- exact top-k via bitonic sort; index set emitted sorted ascending ----------------
__global__ void k_topk(const float* __restrict__ vals, int N, int Ksel, int* __restrict__ outIdx) {
    __shared__ float sv[4096];
    __shared__ int   si[4096];
    int b = blockIdx.x, tid = threadIdx.x, bs = blockDim.x;
    for (int i = tid; i < N; i += bs) { sv[i] = vals[b * N + i]; si[i] = i; }
    for (int k = 2; k <= N; k <<= 1) {
        for (int j = k >> 1; j > 0; j >>= 1) {
            __syncthreads();
            for (int i = tid; i < N; i += bs) {
                int l = i ^ j;
                if (l > i) {
                    float vi = sv[i], vl = sv[l];
                    int ii = si[i], il = si[l];
                    bool lFirst = (vl > vi) || (vl == vi && il < ii);
                    bool sw = ((i & k) == 0) ? lFirst : !lFirst;
                    if (sw) { sv[i] = vl; sv[l] = vi; si[i] = il; si[l] = ii; }
                }
            }
        }
    }
    __syncthreads();
    int* sel = (int*)sv;
    for (int i = tid; i < Ksel; i += bs) sel[i] = si[i];
    for (int k = 2; k <= Ksel; k <<= 1) {
        for (int j = k >> 1; j > 0; j >>= 1) {
            __syncthreads();
            for (int i = tid; i < Ksel; i += bs) {
                int l = i ^ j;
                if (l > i) {
                    int a = sel[i], c = sel[l];
                    bool sw = ((i & k) == 0) ? (c < a) : (c > a);
                    if (sw) { sel[i] = c; sel[l] = a; }
                }
            }
        }
    }
    __syncthreads();
    for (int i = tid; i < Ksel; i += bs) outIdx[b * Ksel + i] = sel[i];
}

// ---------------- gathers / reductions ----------------
__global__ void k_gather_wsel(const float* __restrict__ pw) {
    size_t t = (size_t)blockIdx.x * blockDim.x + threadIdx.x;
    int j = (int)(t & (KI - 1));
    size_t bp = t >> 11;
    int p = (int)(bp & (NP - 1));
    int b = (int)(bp >> 11);
    g_wsel[t] = pw[(size_t)p * NIN + g_iidx[b * KI + j]];
}

__global__ void k_scores() {
    int t = blockIdx.x * blockDim.x + threadIdx.x;
    int b = t >> 11, p = t & (NP - 1);
    const float* q = g_pa + (size_t)b * SS * NP + p;
    float s = 0.f;
    #pragma unroll 4
    for (int i = 0; i < SS; i++) s += q[(size_t)i * NP];
    g_scores[t] = s * (1.f / (float)SS);
}

__global__ void k_gather_pasel() {
    size_t t = (size_t)blockIdx.x * blockDim.x + threadIdx.x;
    int q = (int)(t & (KP - 1));
    size_t bs_ = t >> 10;
    int s = (int)(bs_ & (SS - 1));
    int b = (int)(bs_ >> 11);
    g_pasel[t] = g_pa[((size_t)(b * SS + s)) * NP + g_pidx[b * KP + q]];
}

// poT[b][d][q] = po[pidx[b][q]][d]   (32x32 smem transpose, coalesced both sides)
__global__ void k_build_poT(const float* __restrict__ po) {
    __shared__ float t[32][33];
    int b = blockIdx.z;
    int q0 = blockIdx.x * 32, d0 = blockIdx.y * 32;
    int tx = threadIdx.x, ty = threadIdx.y;
    for (int yy = ty; yy < 32; yy += 8) {
        int p = g_pidx[b * KP + q0 + yy];
        t[yy][tx] = po[(size_t)p * DM + d0 + tx];
    }
    __syncthreads();
    for (int yy = ty; yy < 32; yy += 8)
        g_poT[((size_t)b * DM + d0 + yy) * KP + q0 + tx] = t[tx][yy];
}

// ---------------- launch ----------------
extern "C" void kernel_launch(void* const* d_in, const int* in_sizes, int n_in,
                              void* d_out, int out_size) {
    const float* x   = (const float*)d_in[0];
    const float* W1  = (const float*)d_in[3];
    const float* b1  = (const float*)d_in[4];
    const float* lng = (const float*)d_in[5];
    const float* lnb = (const float*)d_in[6];
    const float* W2  = (const float*)d_in[7];
    const float* b2  = (const float*)d_in[8];
    const float* nk  = (const float*)d_in[9];
    const float* ip  = (const float*)d_in[10];
    const float* pw  = (const float*)d_in[11];
    const float* po  = (const float*)d_in[12];
    float* out = (float*)d_out;

    float *p_logits, *p_scores, *p_selin, *p_wsel, *p_pa, *p_pasel, *p_poT;
    int *p_iidx, *p_pidx;
    cudaGetSymbolAddress((void**)&p_logits, g_logits);
    cudaGetSymbolAddress((void**)&p_scores, g_scores);
    cudaGetSymbolAddress((void**)&p_selin,  g_selin);
    cudaGetSymbolAddress((void**)&p_wsel,   g_wsel);
    cudaGetSymbolAddress((void**)&p_pa,     g_pa);
    cudaGetSymbolAddress((void**)&p_pasel,  g_pasel);
    cudaGetSymbolAddress((void**)&p_poT,    g_poT);
    cudaGetSymbolAddress((void**)&p_iidx,   g_iidx);
    cudaGetSymbolAddress((void**)&p_pidx,   g_pidx);

    cudaFuncSetAttribute(mma_nt<true,  true >, cudaFuncAttributeMaxDynamicSharedMemorySize, SMEM_BYTES);
    cudaFuncSetAttribute(mma_nt<true,  false>, cudaFuncAttributeMaxDynamicSharedMemorySize, SMEM_BYTES);
    cudaFuncSetAttribute(mma_nt<false, false>, cudaFuncAttributeMaxDynamicSharedMemorySize, SMEM_BYTES);

    // launch order keeps a GEMM near index 3-5 so ncu's fixed skip lands on one
    k_rowmax<<<BB * DM / 256, 256>>>(x);                           // 0
    k_router<<<BB, 512>>>(W1, b1, lng, lnb, W2, b2, nk);           // 1
    k_topk<<<BB, 1024>>>(p_logits, NIN, KI, p_iidx);               // 2

    // stage 1: sel_in = gelu(x @ gathered_patterns^T)   [3xFP16 mma.sync]
    mma_nt<true, true><<<dim3(KI / 128, SS / 128, BB), 256, SMEM_BYTES>>>(   // 3
        x, ip, p_selin, p_iidx, KI, DM,
        (size_t)SS * DM, 0, (size_t)SS * KI, KI);

    k_gather_wsel<<<(int)((size_t)BB * NP * KI / 256), 256>>>(pw); // 4

    // stage 2: pa = gelu(sel_in @ W_sel^T)   [3xFP16 mma.sync]
    mma_nt<true, false><<<dim3(NP / 128, SS / 128, BB), 256, SMEM_BYTES>>>(  // 5
        p_selin, p_wsel, p_pa, nullptr, NP, KI,
        (size_t)SS * KI, (size_t)NP * KI, (size_t)SS * NP, 0);

    // process selection
    k_scores<<<BB * NP / 256, 256>>>();                            // 6
    k_topk<<<BB, 1024>>>(p_scores, NP, KP, p_pidx);                // 7
    k_gather_pasel<<<(int)((size_t)BB * SS * KP / 256), 256>>>();  // 8
    k_build_poT<<<dim3(KP / 32, DM / 32, BB), dim3(32, 8)>>>(po);  // 9

    // final: out = pa_sel @ poT^T   [3xFP16 mma.sync]
    mma_nt<false, false><<<dim3(DM / 128, SS / 128, BB), 256, SMEM_BYTES>>>( // 10
        p_pasel, p_poT, out, nullptr, DM, KP,
        (size_t)SS * KP, (size_t)DM * KP, (size_t)SS * DM, 0);
}

// round 10
// speedup vs baseline: 1.3722x; 1.0613x over previous
#include <cuda_runtime.h>
#include <cuda_fp16.h>
#include <math.h>
#include <cstdint>

// Problem constants (fixed by dataset; k_input=2048, k_process=1024 always)
#define BB   8
#define SS   2048
#define DM   1024
#define NIN  4096
#define NP   2048
#define DR   256
#define KI   2048
#define KP   1024

// B-operand scaling (exact power of 2): keeps fp16 lo-terms out of subnormal range
#define BSCALE   32.0f
#define BINV     0.03125f

// ---------------- scratch (static __device__ globals; no allocation) ----------------
__device__ float g_gctx [BB * DM];
__device__ float g_logits[BB * NIN];
__device__ float g_scores[BB * NP];
__device__ int   g_iidx [BB * KI];
__device__ int   g_pidx [BB * KP];
__device__ float g_pa   [(size_t)BB * SS * NP];               // 134 MB (fp32: scores + gather)
__device__ __align__(256) __half g_xHi  [(size_t)BB * SS * DM];
__device__ __align__(256) __half g_xLo  [(size_t)BB * SS * DM];
__device__ __align__(256) __half g_ipHi [(size_t)NIN * DM];
__device__ __align__(256) __half g_ipLo [(size_t)NIN * DM];
__device__ __align__(256) __half g_selinHi[(size_t)BB * SS * KI];
__device__ __align__(256) __half g_selinLo[(size_t)BB * SS * KI];
__device__ __align__(256) __half g_wselHi [(size_t)BB * NP * KI];
__device__ __align__(256) __half g_wselLo [(size_t)BB * NP * KI];
__device__ __align__(256) __half g_paselHi[(size_t)BB * SS * KP];
__device__ __align__(256) __half g_paselLo[(size_t)BB * SS * KP];
__device__ __align__(256) __half g_poTHi  [(size_t)BB * DM * KP];
__device__ __align__(256) __half g_poTLo  [(size_t)BB * DM * KP];

__device__ __forceinline__ float geluf(float v) {
    return 0.5f * v * (1.0f + erff(v * 0.70710678118654752440f));
}
__device__ __forceinline__ uint32_t smem_u32(const void* p) {
    uint32_t a;
    asm("{ .reg .u64 t; cvta.to.shared.u64 t, %1; cvt.u32.u64 %0, t; }" : "=r"(a) : "l"(p));
    return a;
}
__device__ __forceinline__ void cp16(uint32_t dst, const void* src) {
    asm volatile("cp.async.cg.shared.global [%0], [%1], 16;" :: "r"(dst), "l"(src) : "memory");
}
__device__ __forceinline__ void mma16(float* c, const uint32_t* a, const uint32_t* b) {
    asm volatile(
        "mma.sync.aligned.m16n8k16.row.col.f32.f16.f16.f32 "
        "{%0,%1,%2,%3}, {%4,%5,%6,%7}, {%8,%9}, {%0,%1,%2,%3};"
        : "+f"(c[0]), "+f"(c[1]), "+f"(c[2]), "+f"(c[3])
        : "r"(a[0]), "r"(a[1]), "r"(a[2]), "r"(a[3]), "r"(b[0]), "r"(b[1]));
}
#define LDMX4(r0, r1, r2, r3, addr) \
    asm volatile("ldmatrix.sync.aligned.m8n8.x4.shared.b16 {%0,%1,%2,%3}, [%4];" \
        : "=r"(r0), "=r"(r1), "=r"(r2), "=r"(r3) : "r"(addr))

// smem: NSTAGE stages; stage = 4 planes (A_hi, A_lo, B_hi, B_lo), each 128 rows x 64B.
// Swizzle: chunk' = c ^ ((r>>1)&3) -> ldmatrix 8-lane phases hit 8 distinct 16B slots mod 128B.
#define PLB    8192
#define STGB   (4 * PLB)
#define NSTAGE 3
#define SMEM_BYTES (NSTAGE * STGB)   // 98304

// ---------------- 3xFP16 mma.sync GEMM on precomputed hi/lo planes ----------------
// C = act(A * (B)^T) * BINV  (B planes pre-scaled by BSCALE)
// A,B: [rows x K] half planes, row-major K-contig (optional row-gather on B).
// CTA tile 128x128, BK=32, 256 threads (8 warps, 4M x 2N), warp tile 32x64.
// MODE: 0 = fp32 out, no GELU; 1 = fp32 out + GELU; 2 = half hi/lo planes out + GELU.
template<int MODE, bool GATHERB>
__global__ void __launch_bounds__(256) mma_nt_h(
    const __half* __restrict__ AHi, const __half* __restrict__ ALo,
    const __half* __restrict__ BHi, const __half* __restrict__ BLo,
    float* __restrict__ Cf, __half* __restrict__ CHi, __half* __restrict__ CLo,
    const int* __restrict__ gidx, int Ncols, int K,
    size_t sA, size_t sB, size_t sC, int sG)
{
    extern __shared__ __align__(16) char smem[];
    const int tid = threadIdx.x, wid = tid >> 5, lane = tid & 31;
    const int lq = lane >> 2, lr = lane & 3;
    const int wm = wid & 3, wn = wid >> 2;
    const int zb = blockIdx.z;
    AHi += (size_t)zb * sA; ALo += (size_t)zb * sA;
    BHi += (size_t)zb * sB; BLo += (size_t)zb * sB;
    if (MODE == 2) { CHi += (size_t)zb * sC; CLo += (size_t)zb * sC; }
    else           { Cf  += (size_t)zb * sC; }
    const int m0 = blockIdx.y * 128, n0 = blockIdx.x * 128;
    const uint32_t sb = smem_u32(smem);

    // loader: 8 x 16B chunks per thread per stage (2 per plane)
    const __half* src[8]; uint32_t dst[8];
    #pragma unroll
    for (int q = 0; q < 8; q++) {
        int id = tid + 256 * q;
        int plane = id >> 9;           // 0 A_hi, 1 A_lo, 2 B_hi, 3 B_lo
        int pid = id & 511;
        int r = pid >> 2, c = pid & 3;
        const __half* base;
        if (plane == 0)      base = AHi + (size_t)(m0 + r) * K;
        else if (plane == 1) base = ALo + (size_t)(m0 + r) * K;
        else {
            int br = n0 + r;
            int bsrc = GATHERB ? gidx[(size_t)zb * sG + br] : br;
            base = (plane == 2 ? BHi : BLo) + (size_t)bsrc * K;
        }
        src[q] = base + c * 8;
        dst[q] = (uint32_t)(plane * PLB + r * 64 + ((c ^ ((r >> 1) & 3)) * 16));
    }

    // per-lane ldmatrix base addresses (ks toggles via ^32; mf/group via +1024; plane via +PLB)
    const int arow = (lane & 7) + ((lane >> 3) & 1) * 8;
    const int kcs = lane >> 4;
    const int rowA0 = wm * 32 + arow;
    const uint32_t baseA = (uint32_t)(rowA0 * 64 + ((kcs ^ ((rowA0 >> 1) & 3)) * 16));
    const int rowB0 = wn * 64 + arow;
    const uint32_t baseB = (uint32_t)(2 * PLB + rowB0 * 64 + ((kcs ^ ((rowB0 >> 1) & 3)) * 16));

    float acc[2][8][4];
    #pragma unroll
    for (int mf = 0; mf < 2; mf++)
        #pragma unroll
        for (int nf = 0; nf < 8; nf++)
            #pragma unroll
            for (int q = 0; q < 4; q++) acc[mf][nf][q] = 0.f;

    const int T = K >> 5;

    #pragma unroll
    for (int s = 0; s < NSTAGE - 1; s++) {
        if (s < T) {
            #pragma unroll
            for (int q = 0; q < 8; q++) cp16(sb + s * STGB + dst[q], src[q] + s * 32);
        }
        asm volatile("cp.async.commit_group;" ::: "memory");
    }

    int stg = 0;
    for (int i = 0; i < T; i++) {
        asm volatile("cp.async.wait_group %0;" :: "n"(NSTAGE - 2) : "memory");
        __syncthreads();

        {
            int ps = i + NSTAGE - 1;
            int pstg = stg + NSTAGE - 1; if (pstg >= NSTAGE) pstg -= NSTAGE;
            if (ps < T) {
                #pragma unroll
                for (int q = 0; q < 8; q++) cp16(sb + pstg * STGB + dst[q], src[q] + ps * 32);
            }
            asm volatile("cp.async.commit_group;" ::: "memory");
        }

        const uint32_t stgb = sb + stg * STGB;
        #pragma unroll
        for (int ks = 0; ks < 2; ks++) {
            const uint32_t aA = stgb + (baseA ^ (ks << 5));
            const uint32_t aB = stgb + (baseB ^ (ks << 5));
            uint32_t ah[2][4], al[2][4];
            LDMX4(ah[0][0], ah[0][1], ah[0][2], ah[0][3], aA);
            LDMX4(ah[1][0], ah[1][1], ah[1][2], ah[1][3], aA + 1024);
            LDMX4(al[0][0], al[0][1], al[0][2], al[0][3], aA + PLB);
            LDMX4(al[1][0], al[1][1], al[1][2], al[1][3], aA + PLB + 1024);
            uint32_t bh[8][2], bl[8][2];
            #pragma unroll
            for (int g = 0; g < 4; g++) {
                uint32_t t0, t1, t2, t3;
                LDMX4(t0, t1, t2, t3, aB + g * 1024);
                bh[2*g][0] = t0; bh[2*g+1][0] = t1; bh[2*g][1] = t2; bh[2*g+1][1] = t3;
                LDMX4(t0, t1, t2, t3, aB + PLB + g * 1024);
                bl[2*g][0] = t0; bl[2*g+1][0] = t1; bl[2*g][1] = t2; bl[2*g+1][1] = t3;
            }
            #pragma unroll
            for (int mf = 0; mf < 2; mf++)
                #pragma unroll
                for (int nf = 0; nf < 8; nf++) {
                    mma16(acc[mf][nf], ah[mf], bh[nf]);
                    mma16(acc[mf][nf], al[mf], bh[nf]);
                    mma16(acc[mf][nf], ah[mf], bl[nf]);
                }
        }
        if (++stg == NSTAGE) stg = 0;
    }

    // epilogue
    #pragma unroll
    for (int mf = 0; mf < 2; mf++) {
        int row0 = m0 + wm * 32 + mf * 16 + lq;
        #pragma unroll
        for (int nf = 0; nf < 8; nf++) {
            int col = n0 + wn * 64 + nf * 8 + 2 * lr;
            float2 v0, v1;
            v0.x = acc[mf][nf][0] * BINV; v0.y = acc[mf][nf][1] * BINV;
            v1.x = acc[mf][nf][2] * BINV; v1.y = acc[mf][nf][3] * BINV;
            if (MODE >= 1) {
                v0.x = geluf(v0.x); v0.y = geluf(v0.y);
                v1.x = geluf(v1.x); v1.y = geluf(v1.y);
            }
            if (MODE == 2) {
                size_t o0 = (size_t)row0 * Ncols + col;
                size_t o1 = (size_t)(row0 + 8) * Ncols + col;
                __half2 h0 = __floats2half2_rn(v0.x, v0.y);
                float2 f0 = __half22float2(h0);
                __half2 l0 = __floats2half2_rn(v0.x - f0.x, v0.y - f0.y);
                __half2 h1 = __floats2half2_rn(v1.x, v1.y);
                float2 f1 = __half22float2(h1);
                __half2 l1 = __floats2half2_rn(v1.x - f1.x, v1.y - f1.y);
                *(__half2*)(CHi + o0) = h0; *(__half2*)(CLo + o0) = l0;
                *(__half2*)(CHi + o1) = h1; *(__half2*)(CLo + o1) = l1;
            } else {
                *(float2*)(Cf + (size_t)row0 * Ncols + col) = v0;
                *(float2*)(Cf + (size_t)(row0 + 8) * Ncols + col) = v1;
            }
        }
    }
}

// ---------------- fp32 -> (hi, lo) half plane split ----------------
__global__ void k_split(const float* __restrict__ src, __half* __restrict__ dHi,
                        __half* __restrict__ dLo, float scale, size_t n4) {
    size_t t = (size_t)blockIdx.x * blockDim.x + threadIdx.x;
    if (t >= n4) return;
    float4 v = ((const float4*)src)[t];
    v.x *= scale; v.y *= scale; v.z *= scale; v.w *= scale;
    __half2 h0 = __floats2half2_rn(v.x, v.y), h1 = __floats2half2_rn(v.z, v.w);
    float2 f0 = __half22float2(h0), f1 = __half22float2(h1);
    __half2 l0 = __floats2half2_rn(v.x - f0.x, v.y - f0.y);
    __half2 l1 = __floats2half2_rn(v.z - f1.x, v.w - f1.y);
    ((__half2*)dHi)[2 * t] = h0; ((__half2*)dHi)[2 * t + 1] = h1;
    ((__half2*)dLo)[2 * t] = l0; ((__half2*)dLo)[2 * t + 1] = l1;
}

// ---------------- router ----------------
__global__ void k_rowmax(const float* __restrict__ x) {
    int t = blockIdx.x * blockDim.x + threadIdx.x;
    int b = t >> 10, d = t & (DM - 1);
    const float* p = x + (size_t)b * SS * DM + d;
    float m = -INFINITY;
    #pragma unroll 8
    for (int s = 0; s < SS; s++) m = fmaxf(m, p[(size_t)s * DM]);
    g_gctx[t] = m;
}

// fused: mlp1 -> gelu -> LN -> mlp2 -> logits   (one block per batch, 512 thr)
__global__ void __launch_bounds__(512) k_router(
    const float* __restrict__ W1, const float* __restrict__ b1,
    const float* __restrict__ lng, const float* __restrict__ lnb,
    const float* __restrict__ W2, const float* __restrict__ b2,
    const float* __restrict__ nk)
{
    int b = blockIdx.x, tid = threadIdx.x, wid = tid >> 5, lane = tid & 31;
    __shared__ float sg[1024];
    __shared__ float sh[512];
    __shared__ float red[512];
    __shared__ float sq[256];
    sg[tid] = g_gctx[b * 1024 + tid];
    sg[tid + 512] = g_gctx[b * 1024 + 512 + tid];
    __syncthreads();
    for (int oo = 0; oo < 32; oo++) {
        int o = wid * 32 + oo;
        const float* w = W1 + (size_t)o * 1024;
        float s = 0.f;
        for (int k = lane; k < 1024; k += 32) s += sg[k] * w[k];
        #pragma unroll
        for (int off = 16; off; off >>= 1) s += __shfl_xor_sync(0xffffffffu, s, off);
        if (lane == 0) sh[o] = geluf(s + b1[o]);
    }
    __syncthreads();
    float v = sh[tid];
    red[tid] = v;
    for (int s = 256; s; s >>= 1) { __syncthreads(); if (tid < s) red[tid] += red[tid + s]; }
    __syncthreads();
    float mu = red[0] * (1.f / 512.f);
    __syncthreads();
    float dv = v - mu;
    red[tid] = dv * dv;
    for (int s = 256; s; s >>= 1) { __syncthreads(); if (tid < s) red[tid] += red[tid + s]; }
    __syncthreads();
    float var = red[0] * (1.f / 512.f);
    __syncthreads();
    sh[tid] = dv * rsqrtf(var + 1e-5f) * lng[tid] + lnb[tid];
    __syncthreads();
    for (int oo = 0; oo < 16; oo++) {
        int o = wid * 16 + oo;
        const float* w = W2 + (size_t)o * 512;
        float s = 0.f;
        for (int k = lane; k < 512; k += 32) s += sh[k] * w[k];
        #pragma unroll
        for (int off = 16; off; off >>= 1) s += __shfl_xor_sync(0xffffffffu, s, off);
        if (lane == 0) sq[o] = s + b2[o];
    }
    __syncthreads();
    for (int oo = 0; oo < 256; oo++) {
        int n = wid * 256 + oo;
        const float* w = nk + (size_t)n * 256;
        float s = 0.f;
        #pragma unroll
        for (int k = lane; k < 256; k += 32) s += sq[k] * w[k];
        #pragma unroll
        for (int off = 16; off; off >>= 1) s += __shfl_xor_sync(0xffffffffu, s, off);
        if (lane == 0) g_logits[b * 4096 + n] = s * 0.0625f;
    }
}

// ---------------- exact top-k via bitonic sort; index set emitted sorted ascending ----------------
__global__ void k_topk(const float* __restrict__ vals, int N, int Ksel, int* __restrict__ outIdx) {
    __shared__ float sv[4096];
    __shared__ int   si[4096];
    int b = blockIdx.x, tid = threadIdx.x, bs = blockDim.x;
    for (int i = tid; i < N; i += bs) { sv[i] = vals[b * N + i]; si[i] = i; }
    for (int k = 2; k <= N; k <<= 1) {
        for (int j = k >> 1; j > 0; j >>= 1) {
            __syncthreads();
            for (int i = tid; i < N; i += bs) {
                int l = i ^ j;
                if (l > i) {
                    float vi = sv[i], vl = sv[l];
                    int ii = si[i], il = si[l];
                    bool lFirst = (vl > vi) || (vl == vi && il < ii);
                    bool sw = ((i & k) == 0) ? lFirst : !lFirst;
                    if (sw) { sv[i] = vl; sv[l] = vi; si[i] = il; si[l] = ii; }
                }
            }
        }
    }
    __syncthreads();
    int* sel = (int*)sv;
    for (int i = tid; i < Ksel; i += bs) sel[i] = si[i];
    for (int k = 2; k <= Ksel; k <<= 1) {
        for (int j = k >> 1; j > 0; j >>= 1) {
            __syncthreads();
            for (int i = tid; i < Ksel; i += bs) {
                int l = i ^ j;
                if (l > i) {
                    int a = sel[i], c = sel[l];
                    bool sw = ((i & k) == 0) ? (c < a) : (c > a);
                    if (sw) { sel[i] = c; sel[l] = a; }
                }
            }
        }
    }
    __syncthreads();
    for (int i = tid; i < Ksel; i += bs) outIdx[b * Ksel + i] = sel[i];
}

// ---------------- gathers / reductions (emit half hi/lo planes) ----------------
__global__ void k_gather_wsel(const float* __restrict__ pw) {
    size_t t = (size_t)blockIdx.x * blockDim.x + threadIdx.x;
    int j = (int)(t & (KI - 1));
    size_t bp = t >> 11;
    int p = (int)(bp & (NP - 1));
    int b = (int)(bp >> 11);
    float v = pw[(size_t)p * NIN + g_iidx[b * KI + j]] * BSCALE;
    __half h = __float2half_rn(v);
    g_wselHi[t] = h;
    g_wselLo[t] = __float2half_rn(v - __half2float(h));
}

__global__ void k_scores() {
    int t = blockIdx.x * blockDim.x + threadIdx.x;
    int b = t >> 11, p = t & (NP - 1);
    const float* q = g_pa + (size_t)b * SS * NP + p;
    float s = 0.f;
    #pragma unroll 4
    for (int i = 0; i < SS; i++) s += q[(size_t)i * NP];
    g_scores[t] = s * (1.f / (float)SS);
}

__global__ void k_gather_pasel() {
    size_t t = (size_t)blockIdx.x * blockDim.x + threadIdx.x;
    int q = (int)(t & (KP - 1));
    size_t bs_ = t >> 10;
    int s = (int)(bs_ & (SS - 1));
    int b = (int)(bs_ >> 11);
    float v = g_pa[((size_t)(b * SS + s)) * NP + g_pidx[b * KP + q]];
    __half h = __float2half_rn(v);
    g_paselHi[t] = h;
    g_paselLo[t] = __float2half_rn(v - __half2float(h));
}

// poT[b][d][q] = po[pidx[b][q]][d] * BSCALE, as hi/lo planes (32x32 smem transpose)
__global__ void k_build_poT(const float* __restrict__ po) {
    __shared__ float t[32][33];
    int b = blockIdx.z;
    int q0 = blockIdx.x * 32, d0 = blockIdx.y * 32;
    int tx = threadIdx.x, ty = threadIdx.y;
    for (int yy = ty; yy < 32; yy += 8) {
        int p = g_pidx[b * KP + q0 + yy];
        t[yy][tx] = po[(size_t)p * DM + d0 + tx];
    }
    __syncthreads();
    for (int yy = ty; yy < 32; yy += 8) {
        float v = t[tx][yy] * BSCALE;
        size_t idx = ((size_t)b * DM + d0 + yy) * KP + q0 + tx;
        __half h = __float2half_rn(v);
        g_poTHi[idx] = h;
        g_poTLo[idx] = __float2half_rn(v - __half2float(h));
    }
}

// ---------------- launch ----------------
extern "C" void kernel_launch(void* const* d_in, const int* in_sizes, int n_in,
                              void* d_out, int out_size) {
    const float* x   = (const float*)d_in[0];
    const float* W1  = (const float*)d_in[3];
    const float* b1  = (const float*)d_in[4];
    const float* lng = (const float*)d_in[5];
    const float* lnb = (const float*)d_in[6];
    const float* W2  = (const float*)d_in[7];
    const float* b2  = (const float*)d_in[8];
    const float* nk  = (const float*)d_in[9];
    const float* ip  = (const float*)d_in[10];
    const float* pw  = (const float*)d_in[11];
    const float* po  = (const float*)d_in[12];
    float* out = (float*)d_out;

    float *p_logits, *p_scores, *p_pa;
    int *p_iidx, *p_pidx;
    __half *p_xHi, *p_xLo, *p_ipHi, *p_ipLo, *p_selinHi, *p_selinLo;
    __half *p_wselHi, *p_wselLo, *p_paselHi, *p_paselLo, *p_poTHi, *p_poTLo;
    cudaGetSymbolAddress((void**)&p_logits, g_logits);
    cudaGetSymbolAddress((void**)&p_scores, g_scores);
    cudaGetSymbolAddress((void**)&p_pa,     g_pa);
    cudaGetSymbolAddress((void**)&p_iidx,   g_iidx);
    cudaGetSymbolAddress((void**)&p_pidx,   g_pidx);
    cudaGetSymbolAddress((void**)&p_xHi,    g_xHi);
    cudaGetSymbolAddress((void**)&p_xLo,    g_xLo);
    cudaGetSymbolAddress((void**)&p_ipHi,   g_ipHi);
    cudaGetSymbolAddress((void**)&p_ipLo,   g_ipLo);
    cudaGetSymbolAddress((void**)&p_selinHi, g_selinHi);
    cudaGetSymbolAddress((void**)&p_selinLo, g_selinLo);
    cudaGetSymbolAddress((void**)&p_wselHi, g_wselHi);
    cudaGetSymbolAddress((void**)&p_wselLo, g_wselLo);
    cudaGetSymbolAddress((void**)&p_paselHi, g_paselHi);
    cudaGetSymbolAddress((void**)&p_paselLo, g_paselLo);
    cudaGetSymbolAddress((void**)&p_poTHi,  g_poTHi);
    cudaGetSymbolAddress((void**)&p_poTLo,  g_poTLo);

    cudaFuncSetAttribute(mma_nt_h<2, true >, cudaFuncAttributeMaxDynamicSharedMemorySize, SMEM_BYTES);
    cudaFuncSetAttribute(mma_nt_h<1, false>, cudaFuncAttributeMaxDynamicSharedMemorySize, SMEM_BYTES);
    cudaFuncSetAttribute(mma_nt_h<0, false>, cudaFuncAttributeMaxDynamicSharedMemorySize, SMEM_BYTES);

    // router (fp32 exact)
    k_rowmax<<<BB * DM / 256, 256>>>(x);                                     // 0
    k_router<<<BB, 512>>>(W1, b1, lng, lnb, W2, b2, nk);                     // 1
    k_topk<<<BB, 1024>>>(p_logits, NIN, KI, p_iidx);                         // 2

    // operand plane preparation
    k_split<<<(int)(((size_t)BB * SS * DM / 4 + 255) / 256), 256>>>(x, p_xHi, p_xLo, 1.0f, (size_t)BB * SS * DM / 4);        // 3
    k_split<<<(int)(((size_t)NIN * DM / 4 + 255) / 256), 256>>>(ip, p_ipHi, p_ipLo, BSCALE, (size_t)NIN * DM / 4);           // 4

    // stage 1: selin(planes) = gelu(x @ gathered_patterns^T)
    mma_nt_h<2, true><<<dim3(KI / 128, SS / 128, BB), 256, SMEM_BYTES>>>(    // 5
        p_xHi, p_xLo, p_ipHi, p_ipLo, nullptr, p_selinHi, p_selinLo,
        p_iidx, KI, DM, (size_t)SS * DM, 0, (size_t)SS * KI, KI);

    k_gather_wsel<<<(int)((size_t)BB * NP * KI / 256), 256>>>(pw);           // 6

    // stage 2: pa(fp32) = gelu(selin @ wsel^T)
    mma_nt_h<1, false><<<dim3(NP / 128, SS / 128, BB), 256, SMEM_BYTES>>>(   // 7
        p_selinHi, p_selinLo, p_wselHi, p_wselLo, p_pa, nullptr, nullptr,
        nullptr, NP, KI, (size_t)SS * KI, (size_t)NP * KI, (size_t)SS * NP, 0);

    // process selection
    k_scores<<<BB * NP / 256, 256>>>();                                      // 8
    k_topk<<<BB, 1024>>>(p_scores, NP, KP, p_pidx);                          // 9
    k_gather_pasel<<<(int)((size_t)BB * SS * KP / 256), 256>>>();            // 10
    k_build_poT<<<dim3(KP / 32, DM / 32, BB), dim3(32, 8)>>>(po);            // 11

    // final: out(fp32) = pasel @ poT^T
    mma_nt_h<0, false><<<dim3(DM / 128, SS / 128, BB), 256, SMEM_BYTES>>>(   // 12
        p_paselHi, p_paselLo, p_poTHi, p_poTLo, out, nullptr, nullptr,
        nullptr, DM, KP, (size_t)SS * KP, (size_t)DM * KP, (size_t)SS * DM, 0);
}

// round 11
// speedup vs baseline: 1.5124x; 1.1021x over previous
#include <cuda_runtime.h>
#include <cuda_fp16.h>
#include <math.h>
#include <cstdint>

// Problem constants (fixed by dataset; k_input=2048, k_process=1024 always)
#define BB   8
#define SS   2048
#define DM   1024
#define NIN  4096
#define NP   2048
#define DR   256
#define KI   2048
#define KP   1024

// B-operand scaling (exact power of 2): keeps fp16 lo-terms out of subnormal range
#define BSCALE   32.0f
#define BINV     0.03125f

// ---------------- scratch (static __device__ globals; no allocation) ----------------
__device__ float g_pmax [16 * BB * DM];
__device__ float g_logits[BB * NIN];
__device__ float g_scores[BB * NP];
__device__ int   g_iidx [BB * KI];
__device__ int   g_pidx [BB * KP];
__device__ float g_pa   [(size_t)BB * SS * NP];               // 134 MB
__device__ __align__(256) __half g_xHi  [(size_t)BB * SS * DM];
__device__ __align__(256) __half g_xLo  [(size_t)BB * SS * DM];
__device__ __align__(256) __half g_ipHi [(size_t)NIN * DM];
__device__ __align__(256) __half g_ipLo [(size_t)NIN * DM];
__device__ __align__(256) __half g_selinHi[(size_t)BB * SS * KI];
__device__ __align__(256) __half g_selinLo[(size_t)BB * SS * KI];
__device__ __align__(256) __half g_wselHi [(size_t)BB * NP * KI];
__device__ __align__(256) __half g_wselLo [(size_t)BB * NP * KI];
__device__ __align__(256) __half g_paselHi[(size_t)BB * SS * KP];
__device__ __align__(256) __half g_paselLo[(size_t)BB * SS * KP];
__device__ __align__(256) __half g_poTHi  [(size_t)BB * DM * KP];
__device__ __align__(256) __half g_poTLo  [(size_t)BB * DM * KP];

__device__ __forceinline__ float geluf(float v) {
    return 0.5f * v * (1.0f + erff(v * 0.70710678118654752440f));
}
__device__ __forceinline__ uint32_t smem_u32(const void* p) {
    uint32_t a;
    asm("{ .reg .u64 t; cvta.to.shared.u64 t, %1; cvt.u32.u64 %0, t; }" : "=r"(a) : "l"(p));
    return a;
}
__device__ __forceinline__ void cp16(uint32_t dst, const void* src) {
    asm volatile("cp.async.cg.shared.global [%0], [%1], 16;" :: "r"(dst), "l"(src) : "memory");
}
__device__ __forceinline__ void mma16(float* c, const uint32_t* a, const uint32_t* b) {
    asm volatile(
        "mma.sync.aligned.m16n8k16.row.col.f32.f16.f16.f32 "
        "{%0,%1,%2,%3}, {%4,%5,%6,%7}, {%8,%9}, {%0,%1,%2,%3};"
        : "+f"(c[0]), "+f"(c[1]), "+f"(c[2]), "+f"(c[3])
        : "r"(a[0]), "r"(a[1]), "r"(a[2]), "r"(a[3]), "r"(b[0]), "r"(b[1]));
}
#define LDMX4(r0, r1, r2, r3, addr) \
    asm volatile("ldmatrix.sync.aligned.m8n8.x4.shared.b16 {%0,%1,%2,%3}, [%4];" \
        : "=r"(r0), "=r"(r1), "=r"(r2), "=r"(r3) : "r"(addr))

// smem: NSTAGE stages; stage = 4 planes (A_hi, A_lo, B_hi, B_lo), each 128 rows x 128B (BK=64).
// Swizzle: chunk' = c ^ (r & 7) over 8 x 16B chunks -> conflict-free for cp.async stores
// and for every ldmatrix phase (all fragment row bases are multiples of 8).
#define PLB    16384
#define STGB   (4 * PLB)
#define NSTAGE 3
#define SMEM_BYTES (NSTAGE * STGB)   // 196608

// ---------------- 3xFP16 mma.sync GEMM on precomputed hi/lo planes ----------------
// C = act(A * B^T) * BINV  (B planes pre-scaled by BSCALE)
// CTA tile 128x128, BK=64, 256 threads (8 warps, 4M x 2N), warp tile 32x64.
// MODE: 0 = fp32 out; 1 = fp32 out + GELU; 2 = half hi/lo planes out + GELU.
template<int MODE, bool GATHERB>
__global__ void __launch_bounds__(256) mma_nt_h(
    const __half* __restrict__ AHi, const __half* __restrict__ ALo,
    const __half* __restrict__ BHi, const __half* __restrict__ BLo,
    float* __restrict__ Cf, __half* __restrict__ CHi, __half* __restrict__ CLo,
    const int* __restrict__ gidx, int Ncols, int K,
    size_t sA, size_t sB, size_t sC, int sG)
{
    extern __shared__ __align__(16) char smem[];
    const int tid = threadIdx.x, wid = tid >> 5, lane = tid & 31;
    const int lq = lane >> 2, lr = lane & 3;
    const int wm = wid & 3, wn = wid >> 2;
    const int zb = blockIdx.z;
    AHi += (size_t)zb * sA; ALo += (size_t)zb * sA;
    BHi += (size_t)zb * sB; BLo += (size_t)zb * sB;
    if (MODE == 2) { CHi += (size_t)zb * sC; CLo += (size_t)zb * sC; }
    else           { Cf  += (size_t)zb * sC; }
    const int m0 = blockIdx.y * 128, n0 = blockIdx.x * 128;
    const uint32_t sb = smem_u32(smem);

    // loader: 4 (row, chunk) pairs per thread; each pair serves all 4 planes
    int aOff[4], bOff[4]; uint32_t dstA[4];
    #pragma unroll
    for (int q = 0; q < 4; q++) {
        int pid = q * 256 + tid;
        int r = pid >> 3, c = pid & 7;
        aOff[q] = (m0 + r) * K + c * 8;
        int br = n0 + r;
        int bsrc = GATHERB ? gidx[(size_t)zb * sG + br] : br;
        bOff[q] = bsrc * K + c * 8;
        dstA[q] = (uint32_t)(r * 128 + ((c ^ (r & 7)) * 16));
    }

    // ldmatrix per-lane bases
    const int l15 = lane & 15, cb = lane >> 4, rm = lane & 7;
    const uint32_t roffA = (uint32_t)((wm * 32 + l15) * 128);
    const uint32_t roffB = (uint32_t)(2 * PLB + (wn * 64 + l15) * 128);

    float acc[2][8][4];
    #pragma unroll
    for (int mf = 0; mf < 2; mf++)
        #pragma unroll
        for (int nf = 0; nf < 8; nf++)
            #pragma unroll
            for (int q = 0; q < 4; q++) acc[mf][nf][q] = 0.f;

    const int T = K >> 6;   // BK = 64

    #pragma unroll
    for (int s = 0; s < NSTAGE - 1; s++) {
        if (s < T) {
            int kb = s * 64;
            uint32_t so = sb + s * STGB;
            #pragma unroll
            for (int q = 0; q < 4; q++) {
                cp16(so + dstA[q],           AHi + aOff[q] + kb);
                cp16(so + PLB + dstA[q],     ALo + aOff[q] + kb);
                cp16(so + 2 * PLB + dstA[q], BHi + bOff[q] + kb);
                cp16(so + 3 * PLB + dstA[q], BLo + bOff[q] + kb);
            }
        }
        asm volatile("cp.async.commit_group;" ::: "memory");
    }

    int stg = 0;
    for (int i = 0; i < T; i++) {
        asm volatile("cp.async.wait_group %0;" :: "n"(NSTAGE - 2) : "memory");
        __syncthreads();

        {
            int ps = i + NSTAGE - 1;
            int pstg = stg + NSTAGE - 1; if (pstg >= NSTAGE) pstg -= NSTAGE;
            if (ps < T) {
                int kb = ps * 64;
                uint32_t so = sb + pstg * STGB;
                #pragma unroll
                for (int q = 0; q < 4; q++) {
                    cp16(so + dstA[q],           AHi + aOff[q] + kb);
                    cp16(so + PLB + dstA[q],     ALo + aOff[q] + kb);
                    cp16(so + 2 * PLB + dstA[q], BHi + bOff[q] + kb);
                    cp16(so + 3 * PLB + dstA[q], BLo + bOff[q] + kb);
                }
            }
            asm volatile("cp.async.commit_group;" ::: "memory");
        }

        const uint32_t stgb = sb + stg * STGB;
        #pragma unroll
        for (int ks = 0; ks < 4; ks++) {
            const uint32_t sw = (uint32_t)((((2 * ks + cb) ^ rm)) * 16);
            const uint32_t aA = stgb + roffA + sw;
            const uint32_t aB = stgb + roffB + sw;
            uint32_t ah[2][4], al[2][4];
            LDMX4(ah[0][0], ah[0][1], ah[0][2], ah[0][3], aA);
            LDMX4(ah[1][0], ah[1][1], ah[1][2], ah[1][3], aA + 2048);
            LDMX4(al[0][0], al[0][1], al[0][2], al[0][3], aA + PLB);
            LDMX4(al[1][0], al[1][1], al[1][2], al[1][3], aA + PLB + 2048);
            uint32_t bh[8][2], bl[8][2];
            #pragma unroll
            for (int g = 0; g < 4; g++) {
                uint32_t t0, t1, t2, t3;
                LDMX4(t0, t1, t2, t3, aB + g * 2048);
                bh[2*g][0] = t0; bh[2*g+1][0] = t1; bh[2*g][1] = t2; bh[2*g+1][1] = t3;
                LDMX4(t0, t1, t2, t3, aB + PLB + g * 2048);
                bl[2*g][0] = t0; bl[2*g+1][0] = t1; bl[2*g][1] = t2; bl[2*g+1][1] = t3;
            }
            #pragma unroll
            for (int mf = 0; mf < 2; mf++)
                #pragma unroll
                for (int nf = 0; nf < 8; nf++) {
                    mma16(acc[mf][nf], ah[mf], bh[nf]);
                    mma16(acc[mf][nf], al[mf], bh[nf]);
                    mma16(acc[mf][nf], ah[mf], bl[nf]);
                }
        }
        if (++stg == NSTAGE) stg = 0;
    }

    // epilogue
    #pragma unroll
    for (int mf = 0; mf < 2; mf++) {
        int row0 = m0 + wm * 32 + mf * 16 + lq;
        #pragma unroll
        for (int nf = 0; nf < 8; nf++) {
            int col = n0 + wn * 64 + nf * 8 + 2 * lr;
            float2 v0, v1;
            v0.x = acc[mf][nf][0] * BINV; v0.y = acc[mf][nf][1] * BINV;
            v1.x = acc[mf][nf][2] * BINV; v1.y = acc[mf][nf][3] * BINV;
            if (MODE >= 1) {
                v0.x = geluf(v0.x); v0.y = geluf(v0.y);
                v1.x = geluf(v1.x); v1.y = geluf(v1.y);
            }
            if (MODE == 2) {
                size_t o0 = (size_t)row0 * Ncols + col;
                size_t o1 = (size_t)(row0 + 8) * Ncols + col;
                __half2 h0 = __floats2half2_rn(v0.x, v0.y);
                float2 f0 = __half22float2(h0);
                __half2 l0 = __floats2half2_rn(v0.x - f0.x, v0.y - f0.y);
                __half2 h1 = __floats2half2_rn(v1.x, v1.y);
                float2 f1 = __half22float2(h1);
                __half2 l1 = __floats2half2_rn(v1.x - f1.x, v1.y - f1.y);
                *(__half2*)(CHi + o0) = h0; *(__half2*)(CLo + o0) = l0;
                *(__half2*)(CHi + o1) = h1; *(__half2*)(CLo + o1) = l1;
            } else {
                *(float2*)(Cf + (size_t)row0 * Ncols + col) = v0;
                *(float2*)(Cf + (size_t)(row0 + 8) * Ncols + col) = v1;
            }
        }
    }
}

// ---------------- fused prep: x partial-max + x hi/lo planes + ip hi/lo planes ----------------
__global__ void k_prep(const float* __restrict__ x, const float* __restrict__ ip) {
    int tid = threadIdx.x;
    if (blockIdx.x < 128) {
        int b = blockIdx.x >> 4, sc = blockIdx.x & 15;
        int s0 = sc * 128;
        #pragma unroll
        for (int dg = 0; dg < 4; dg++) {
            int d = dg * 256 + tid;
            size_t base = ((size_t)(b * SS + s0)) * DM + d;
            const float* px = x + base;
            __half* ph = g_xHi + base;
            __half* pl = g_xLo + base;
            float m = -INFINITY;
            #pragma unroll 4
            for (int s = 0; s < 128; s++) {
                float v = px[(size_t)s * DM];
                m = fmaxf(m, v);
                __half h = __float2half_rn(v);
                ph[(size_t)s * DM] = h;
                pl[(size_t)s * DM] = __float2half_rn(v - __half2float(h));
            }
            g_pmax[(sc * BB + b) * DM + d] = m;
        }
    } else {
        size_t t = (size_t)(blockIdx.x - 128) * 256 + tid;   // NIN*DM/4 float4s
        float4 v = ((const float4*)ip)[t];
        v.x *= BSCALE; v.y *= BSCALE; v.z *= BSCALE; v.w *= BSCALE;
        __half2 h0 = __floats2half2_rn(v.x, v.y), h1 = __floats2half2_rn(v.z, v.w);
        float2 f0 = __half22float2(h0), f1 = __half22float2(h1);
        __half2 l0 = __floats2half2_rn(v.x - f0.x, v.y - f0.y);
        __half2 l1 = __floats2half2_rn(v.z - f1.x, v.w - f1.y);
        ((__half2*)g_ipHi)[2 * t] = h0; ((__half2*)g_ipHi)[2 * t + 1] = h1;
        ((__half2*)g_ipLo)[2 * t] = l0; ((__half2*)g_ipLo)[2 * t + 1] = l1;
    }
}

// ---------------- router: pmax reduce -> mlp1 -> gelu -> LN -> mlp2 -> logits ----------------
__global__ void __launch_bounds__(512) k_router(
    const float* __restrict__ W1, const float* __restrict__ b1,
    const float* __restrict__ lng, const float* __restrict__ lnb,
    const float* __restrict__ W2, const float* __restrict__ b2,
    const float* __restrict__ nk)
{
    int b = blockIdx.x, tid = threadIdx.x, wid = tid >> 5, lane = tid & 31;
    __shared__ float sg[1024];
    __shared__ float sh[512];
    __shared__ float red[512];
    __shared__ float sq[256];
    for (int d = tid; d < 1024; d += 512) {
        float m = -INFINITY;
        #pragma unroll
        for (int sc = 0; sc < 16; sc++) m = fmaxf(m, g_pmax[(sc * BB + b) * DM + d]);
        sg[d] = m;
    }
    __syncthreads();
    for (int oo = 0; oo < 32; oo++) {
        int o = wid * 32 + oo;
        const float* w = W1 + (size_t)o * 1024;
        float s = 0.f;
        for (int k = lane; k < 1024; k += 32) s += sg[k] * w[k];
        #pragma unroll
        for (int off = 16; off; off >>= 1) s += __shfl_xor_sync(0xffffffffu, s, off);
        if (lane == 0) sh[o] = geluf(s + b1[o]);
    }
    __syncthreads();
    float v = sh[tid];
    red[tid] = v;
    for (int s = 256; s; s >>= 1) { __syncthreads(); if (tid < s) red[tid] += red[tid + s]; }
    __syncthreads();
    float mu = red[0] * (1.f / 512.f);
    __syncthreads();
    float dv = v - mu;
    red[tid] = dv * dv;
    for (int s = 256; s; s >>= 1) { __syncthreads(); if (tid < s) red[tid] += red[tid + s]; }
    __syncthreads();
    float var = red[0] * (1.f / 512.f);
    __syncthreads();
    sh[tid] = dv * rsqrtf(var + 1e-5f) * lng[tid] + lnb[tid];
    __syncthreads();
    for (int oo = 0; oo < 16; oo++) {
        int o = wid * 16 + oo;
        const float* w = W2 + (size_t)o * 512;
        float s = 0.f;
        for (int k = lane; k < 512; k += 32) s += sh[k] * w[k];
        #pragma unroll
        for (int off = 16; off; off >>= 1) s += __shfl_xor_sync(0xffffffffu, s, off);
        if (lane == 0) sq[o] = s + b2[o];
    }
    __syncthreads();
    for (int oo = 0; oo < 256; oo++) {
        int n = wid * 256 + oo;
        const float* w = nk + (size_t)n * 256;
        float s = 0.f;
        #pragma unroll
        for (int k = lane; k < 256; k += 32) s += sq[k] * w[k];
        #pragma unroll
        for (int off = 16; off; off >>= 1) s += __shfl_xor_sync(0xffffffffu, s, off);
        if (lane == 0) g_logits[b * 4096 + n] = s * 0.0625f;
    }
}

// ---------------- exact top-k via bitonic sort; index set emitted sorted ascending ----------------
__global__ void k_topk(const float* __restrict__ vals, int N, int Ksel, int* __restrict__ outIdx) {
    __shared__ float sv[4096];
    __shared__ int   si[4096];
    int b = blockIdx.x, tid = threadIdx.x, bs = blockDim.x;
    for (int i = tid; i < N; i += bs) { sv[i] = vals[b * N + i]; si[i] = i; }
    for (int k = 2; k <= N; k <<= 1) {
        for (int j = k >> 1; j > 0; j >>= 1) {
            __syncthreads();
            for (int i = tid; i < N; i += bs) {
                int l = i ^ j;
                if (l > i) {
                    float vi = sv[i], vl = sv[l];
                    int ii = si[i], il = si[l];
                    bool lFirst = (vl > vi) || (vl == vi && il < ii);
                    bool sw = ((i & k) == 0) ? lFirst : !lFirst;
                    if (sw) { sv[i] = vl; sv[l] = vi; si[i] = il; si[l] = ii; }
                }
            }
        }
    }
    __syncthreads();
    int* sel = (int*)sv;
    for (int i = tid; i < Ksel; i += bs) sel[i] = si[i];
    for (int k = 2; k <= Ksel; k <<= 1) {
        for (int j = k >> 1; j > 0; j >>= 1) {
            __syncthreads();
            for (int i = tid; i < Ksel; i += bs) {
                int l = i ^ j;
                if (l > i) {
                    int a = sel[i], c = sel[l];
                    bool sw = ((i & k) == 0) ? (c < a) : (c > a);
                    if (sw) { sel[i] = c; sel[l] = a; }
                }
            }
        }
    }
    __syncthreads();
    for (int i = tid; i < Ksel; i += bs) outIdx[b * Ksel + i] = sel[i];
}

// ---------------- gathers / reductions (emit half hi/lo planes) ----------------
__global__ void k_gather_wsel(const float* __restrict__ pw) {
    size_t t = (size_t)blockIdx.x * blockDim.x + threadIdx.x;
    int j = (int)(t & (KI - 1));
    size_t bp = t >> 11;
    int p = (int)(bp & (NP - 1));
    int b = (int)(bp >> 11);
    float v = pw[(size_t)p * NIN + g_iidx[b * KI + j]] * BSCALE;
    __half h = __float2half_rn(v);
    g_wselHi[t] = h;
    g_wselLo[t] = __float2half_rn(v - __half2float(h));
}

__global__ void k_scores() {
    int t = blockIdx.x * blockDim.x + threadIdx.x;
    int b = t >> 11, p = t & (NP - 1);
    const float* q = g_pa + (size_t)b * SS * NP + p;
    float s = 0.f;
    #pragma unroll 4
    for (int i = 0; i < SS; i++) s += q[(size_t)i * NP];
    g_scores[t] = s * (1.f / (float)SS);
}

__global__ void k_gather_pasel() {
    size_t t = (size_t)blockIdx.x * blockDim.x + threadIdx.x;
    int q = (int)(t & (KP - 1));
    size_t bs_ = t >> 10;
    int s = (int)(bs_ & (SS - 1));
    int b = (int)(bs_ >> 11);
    float v = g_pa[((size_t)(b * SS + s)) * NP + g_pidx[b * KP + q]];
    __half h = __float2half_rn(v);
    g_paselHi[t] = h;
    g_paselLo[t] = __float2half_rn(v - __half2float(h));
}

// poT[b][d][q] = po[pidx[b][q]][d] * BSCALE, as hi/lo planes (32x32 smem transpose)
__global__ void k_build_poT(const float* __restrict__ po) {
    __shared__ float t[32][33];
    int b = blockIdx.z;
    int q0 = blockIdx.x * 32, d0 = blockIdx.y * 32;
    int tx = threadIdx.x, ty = threadIdx.y;
    for (int yy = ty; yy < 32; yy += 8) {
        int p = g_pidx[b * KP + q0 + yy];
        t[yy][tx] = po[(size_t)p * DM + d0 + tx];
    }
    __syncthreads();
    for (int yy = ty; yy < 32; yy += 8) {
        float v = t[tx][yy] * BSCALE;
        size_t idx = ((size_t)b * DM + d0 + yy) * KP + q0 + tx;
        __half h = __float2half_rn(v);
        g_poTHi[idx] = h;
        g_poTLo[idx] = __float2half_rn(v - __half2float(h));
    }
}

// ---------------- launch ----------------
extern "C" void kernel_launch(void* const* d_in, const int* in_sizes, int n_in,
                              void* d_out, int out_size) {
    const float* x   = (const float*)d_in[0];
    const float* W1  = (const float*)d_in[3];
    const float* b1  = (const float*)d_in[4];
    const float* lng = (const float*)d_in[5];
    const float* lnb = (const float*)d_in[6];
    const float* W2  = (const float*)d_in[7];
    const float* b2  = (const float*)d_in[8];
    const float* nk  = (const float*)d_in[9];
    const float* ip  = (const float*)d_in[10];
    const float* pw  = (const float*)d_in[11];
    const float* po  = (const float*)d_in[12];
    float* out = (float*)d_out;

    float *p_logits, *p_scores, *p_pa;
    int *p_iidx, *p_pidx;
    __half *p_xHi, *p_xLo, *p_ipHi, *p_ipLo, *p_selinHi, *p_selinLo;
    __half *p_wselHi, *p_wselLo, *p_paselHi, *p_paselLo, *p_poTHi, *p_poTLo;
    cudaGetSymbolAddress((void**)&p_logits, g_logits);
    cudaGetSymbolAddress((void**)&p_scores, g_scores);
    cudaGetSymbolAddress((void**)&p_pa,     g_pa);
    cudaGetSymbolAddress((void**)&p_iidx,   g_iidx);
    cudaGetSymbolAddress((void**)&p_pidx,   g_pidx);
    cudaGetSymbolAddress((void**)&p_xHi,    g_xHi);
    cudaGetSymbolAddress((void**)&p_xLo,    g_xLo);
    cudaGetSymbolAddress((void**)&p_ipHi,   g_ipHi);
    cudaGetSymbolAddress((void**)&p_ipLo,   g_ipLo);
    cudaGetSymbolAddress((void**)&p_selinHi, g_selinHi);
    cudaGetSymbolAddress((void**)&p_selinLo, g_selinLo);
    cudaGetSymbolAddress((void**)&p_wselHi, g_wselHi);
    cudaGetSymbolAddress((void**)&p_wselLo, g_wselLo);
    cudaGetSymbolAddress((void**)&p_paselHi, g_paselHi);
    cudaGetSymbolAddress((void**)&p_paselLo, g_paselLo);
    cudaGetSymbolAddress((void**)&p_poTHi,  g_poTHi);
    cudaGetSymbolAddress((void**)&p_poTLo,  g_poTLo);

    cudaFuncSetAttribute(mma_nt_h<2, true >, cudaFuncAttributeMaxDynamicSharedMemorySize, SMEM_BYTES);
    cudaFuncSetAttribute(mma_nt_h<1, false>, cudaFuncAttributeMaxDynamicSharedMemorySize, SMEM_BYTES);
    cudaFuncSetAttribute(mma_nt_h<0, false>, cudaFuncAttributeMaxDynamicSharedMemorySize, SMEM_BYTES);

    // 0: fused prep (x partial-max + x planes + ip planes)
    k_prep<<<128 + (int)((size_t)NIN * DM / 4 / 256), 256>>>(x, ip);
    // 1: router
    k_router<<<BB, 512>>>(W1, b1, lng, lnb, W2, b2, nk);
    // 2: input top-k
    k_topk<<<BB, 1024>>>(p_logits, NIN, KI, p_iidx);

    // 3: gemm1 (profiled slot): selin(planes) = gelu(x @ gathered_patterns^T)
    mma_nt_h<2, true><<<dim3(KI / 128, SS / 128, BB), 256, SMEM_BYTES>>>(
        p_xHi, p_xLo, p_ipHi, p_ipLo, nullptr, p_selinHi, p_selinLo,
        p_iidx, KI, DM, (size_t)SS * DM, 0, (size_t)SS * KI, KI);

    // 4: gather pw columns -> wsel planes
    k_gather_wsel<<<(int)((size_t)BB * NP * KI / 256), 256>>>(pw);

    // 5: gemm2: pa(fp32) = gelu(selin @ wsel^T)
    mma_nt_h<1, false><<<dim3(NP / 128, SS / 128, BB), 256, SMEM_BYTES>>>(
        p_selinHi, p_selinLo, p_wselHi, p_wselLo, p_pa, nullptr, nullptr,
        nullptr, NP, KI, (size_t)SS * KI, (size_t)NP * KI, (size_t)SS * NP, 0);

    // 6-9: process selection + operand prep
    k_scores<<<BB * NP / 256, 256>>>();
    k_topk<<<BB, 1024>>>(p_scores, NP, KP, p_pidx);
    k_gather_pasel<<<(int)((size_t)BB * SS * KP / 256), 256>>>();
    k_build_poT<<<dim3(KP / 32, DM / 32, BB), dim3(32, 8)>>>(po);

    // 10: gemm3: out(fp32) = pasel @ poT^T
    mma_nt_h<0, false><<<dim3(DM / 128, SS / 128, BB), 256, SMEM_BYTES>>>(
        p_paselHi, p_paselLo, p_poTHi, p_poTLo, out, nullptr, nullptr,
        nullptr, DM, KP, (size_t)SS * KP, (size_t)DM * KP, (size_t)SS * DM, 0);
}

// round 12
// speedup vs baseline: 1.5687x; 1.0372x over previous
#include <cuda_runtime.h>
#include <cuda_fp16.h>
#include <math.h>
#include <cstdint>

// Problem constants (fixed by dataset; k_input=2048, k_process=1024 always)
#define BB   8
#define SS   2048
#define DM   1024
#define NIN  4096
#define NP   2048
#define DR   256
#define KI   2048
#define KP   1024

#define BSCALE   32.0f
#define BINV     0.03125f

// ---------------- scratch (static __device__ globals; no allocation) ----------------
__device__ float g_pmax [16 * BB * DM];
__device__ float g_logits[BB * NIN];
__device__ float g_scores[BB * NP];
__device__ int   g_iidx [BB * KI];
__device__ int   g_pidx [BB * KP];
__device__ float g_pa   [(size_t)BB * SS * NP];
__device__ __align__(256) __half g_xHi  [(size_t)BB * SS * DM];
__device__ __align__(256) __half g_xLo  [(size_t)BB * SS * DM];
__device__ __align__(256) __half g_ipHi [(size_t)NIN * DM];
__device__ __align__(256) __half g_ipLo [(size_t)NIN * DM];
__device__ __align__(256) __half g_selinHi[(size_t)BB * SS * KI];
__device__ __align__(256) __half g_selinLo[(size_t)BB * SS * KI];
__device__ __align__(256) __half g_wselHi [(size_t)BB * NP * KI];
__device__ __align__(256) __half g_wselLo [(size_t)BB * NP * KI];
__device__ __align__(256) __half g_paselHi[(size_t)BB * SS * KP];
__device__ __align__(256) __half g_paselLo[(size_t)BB * SS * KP];
__device__ __align__(256) __half g_poTHi  [(size_t)BB * DM * KP];
__device__ __align__(256) __half g_poTLo  [(size_t)BB * DM * KP];

__device__ __forceinline__ float geluf(float v) {
    return 0.5f * v * (1.0f + erff(v * 0.70710678118654752440f));
}
__device__ __forceinline__ uint32_t smem_u32(const void* p) {
    uint32_t a;
    asm("{ .reg .u64 t; cvta.to.shared.u64 t, %1; cvt.u32.u64 %0, t; }" : "=r"(a) : "l"(p));
    return a;
}
__device__ __forceinline__ void cp16(uint32_t dst, const void* src) {
    asm volatile("cp.async.cg.shared.global [%0], [%1], 16;" :: "r"(dst), "l"(src) : "memory");
}
__device__ __forceinline__ void mma16(float* c, const uint32_t* a, const uint32_t* b) {
    asm volatile(
        "mma.sync.aligned.m16n8k16.row.col.f32.f16.f16.f32 "
        "{%0,%1,%2,%3}, {%4,%5,%6,%7}, {%8,%9}, {%0,%1,%2,%3};"
        : "+f"(c[0]), "+f"(c[1]), "+f"(c[2]), "+f"(c[3])
        : "r"(a[0]), "r"(a[1]), "r"(a[2]), "r"(a[3]), "r"(b[0]), "r"(b[1]));
}
#define LDMX4(r0, r1, r2, r3, addr) \
    asm volatile("ldmatrix.sync.aligned.m8n8.x4.shared.b16 {%0,%1,%2,%3}, [%4];" \
        : "=r"(r0), "=r"(r1), "=r"(r2), "=r"(r3) : "r"(addr))

// smem: NSTAGE=2 stages; stage = A_hi[32K] A_lo[32K] B_hi[16K] B_lo[16K] = 96KB.
// BK=64, rows of 128B, swizzle chunk' = c ^ (r & 7) over 8 x 16B chunks (conflict-free
// for cp.async stores and all ldmatrix phases; every fragment row base == 0 mod 8).
#define APL    32768
#define BPL    16384
#define BOFF   (2 * APL)
#define STGB   (2 * APL + 2 * BPL)     // 98304
#define NSTAGE 2
#define SMEM_BYTES (NSTAGE * STGB)     // 196608

// ---------------- 3xFP16 mma.sync GEMM on precomputed hi/lo planes ----------------
// C = act(A * B^T) * BINV  (B planes pre-scaled by BSCALE)
// CTA tile 256x128, BK=64, 512 threads (16 warps, 8M x 2N), warp tile 32x64.
// MODE: 0 = fp32 out; 1 = fp32 out + GELU; 2 = half hi/lo planes out + GELU.
template<int MODE, bool GATHERB>
__global__ void __launch_bounds__(512) mma_nt_h(
    const __half* __restrict__ AHi, const __half* __restrict__ ALo,
    const __half* __restrict__ BHi, const __half* __restrict__ BLo,
    float* __restrict__ Cf, __half* __restrict__ CHi, __half* __restrict__ CLo,
    const int* __restrict__ gidx, int Ncols, int K,
    size_t sA, size_t sB, size_t sC, int sG)
{
    extern __shared__ __align__(16) char smem[];
    const int tid = threadIdx.x, wid = tid >> 5, lane = tid & 31;
    const int lq = lane >> 2, lr = lane & 3;
    const int wm = wid & 7, wn = wid >> 3;
    const int zb = blockIdx.z;
    AHi += (size_t)zb * sA; ALo += (size_t)zb * sA;
    BHi += (size_t)zb * sB; BLo += (size_t)zb * sB;
    if (MODE == 2) { CHi += (size_t)zb * sC; CLo += (size_t)zb * sC; }
    else           { Cf  += (size_t)zb * sC; }
    const int m0 = blockIdx.y * 256, n0 = blockIdx.x * 128;
    const uint32_t sb = smem_u32(smem);

    // loader: A = 4 (row,chunk) pairs (256 rows x 8 chunks / 512 thr), B = 2 pairs
    int aOff[4], bOff[2]; uint32_t dstA[4], dstB[2];
    #pragma unroll
    for (int q = 0; q < 4; q++) {
        int pid = q * 512 + tid;
        int r = pid >> 3, c = pid & 7;
        aOff[q] = (m0 + r) * K + c * 8;
        dstA[q] = (uint32_t)(r * 128 + ((c ^ (r & 7)) * 16));
    }
    #pragma unroll
    for (int q = 0; q < 2; q++) {
        int pid = q * 512 + tid;
        int r = pid >> 3, c = pid & 7;
        int br = n0 + r;
        int bsrc = GATHERB ? gidx[(size_t)zb * sG + br] : br;
        bOff[q] = bsrc * K + c * 8;
        dstB[q] = (uint32_t)(BOFF + r * 128 + ((c ^ (r & 7)) * 16));
    }

    // ldmatrix per-lane bases
    const int l15 = lane & 15, cb = lane >> 4, rm = lane & 7;
    const uint32_t roffA = (uint32_t)((wm * 32 + l15) * 128);
    const uint32_t roffB = (uint32_t)(BOFF + (wn * 64 + l15) * 128);

    float acc[2][8][4];
    #pragma unroll
    for (int mf = 0; mf < 2; mf++)
        #pragma unroll
        for (int nf = 0; nf < 8; nf++)
            #pragma unroll
            for (int q = 0; q < 4; q++) acc[mf][nf][q] = 0.f;

    const int T = K >> 6;   // BK = 64

    // prologue: stage 0
    {
        #pragma unroll
        for (int q = 0; q < 4; q++) {
            cp16(sb + dstA[q],       AHi + aOff[q]);
            cp16(sb + APL + dstA[q], ALo + aOff[q]);
        }
        #pragma unroll
        for (int q = 0; q < 2; q++) {
            cp16(sb + dstB[q],       BHi + bOff[q]);
            cp16(sb + BPL + dstB[q], BLo + bOff[q]);
        }
        asm volatile("cp.async.commit_group;" ::: "memory");
    }

    int stg = 0;
    for (int i = 0; i < T; i++) {
        asm volatile("cp.async.wait_group 0;" ::: "memory");
        __syncthreads();

        // prefetch next stage
        {
            int ps = i + 1;
            if (ps < T) {
                int kb = ps * 64;
                uint32_t so = sb + (stg ^ 1) * STGB;
                #pragma unroll
                for (int q = 0; q < 4; q++) {
                    cp16(so + dstA[q],       AHi + aOff[q] + kb);
                    cp16(so + APL + dstA[q], ALo + aOff[q] + kb);
                }
                #pragma unroll
                for (int q = 0; q < 2; q++) {
                    cp16(so + dstB[q],       BHi + bOff[q] + kb);
                    cp16(so + BPL + dstB[q], BLo + bOff[q] + kb);
                }
            }
            asm volatile("cp.async.commit_group;" ::: "memory");
        }

        const uint32_t stgb = sb + stg * STGB;
        #pragma unroll
        for (int ks = 0; ks < 4; ks++) {
            const uint32_t sw = (uint32_t)((((2 * ks + cb) ^ rm)) * 16);
            const uint32_t aA = stgb + roffA + sw;
            const uint32_t aB = stgb + roffB + sw;
            uint32_t ah[2][4], al[2][4];
            LDMX4(ah[0][0], ah[0][1], ah[0][2], ah[0][3], aA);
            LDMX4(ah[1][0], ah[1][1], ah[1][2], ah[1][3], aA + 2048);
            LDMX4(al[0][0], al[0][1], al[0][2], al[0][3], aA + APL);
            LDMX4(al[1][0], al[1][1], al[1][2], al[1][3], aA + APL + 2048);
            uint32_t bh[8][2], bl[8][2];
            #pragma unroll
            for (int g = 0; g < 4; g++) {
                uint32_t t0, t1, t2, t3;
                LDMX4(t0, t1, t2, t3, aB + g * 2048);
                bh[2*g][0] = t0; bh[2*g+1][0] = t1; bh[2*g][1] = t2; bh[2*g+1][1] = t3;
                LDMX4(t0, t1, t2, t3, aB + BPL + g * 2048);
                bl[2*g][0] = t0; bl[2*g+1][0] = t1; bl[2*g][1] = t2; bl[2*g+1][1] = t3;
            }
            #pragma unroll
            for (int mf = 0; mf < 2; mf++)
                #pragma unroll
                for (int nf = 0; nf < 8; nf++) {
                    mma16(acc[mf][nf], ah[mf], bh[nf]);
                    mma16(acc[mf][nf], al[mf], bh[nf]);
                    mma16(acc[mf][nf], ah[mf], bl[nf]);
                }
        }
        stg ^= 1;
    }

    // epilogue
    #pragma unroll
    for (int mf = 0; mf < 2; mf++) {
        int row0 = m0 + wm * 32 + mf * 16 + lq;
        #pragma unroll
        for (int nf = 0; nf < 8; nf++) {
            int col = n0 + wn * 64 + nf * 8 + 2 * lr;
            float2 v0, v1;
            v0.x = acc[mf][nf][0] * BINV; v0.y = acc[mf][nf][1] * BINV;
            v1.x = acc[mf][nf][2] * BINV; v1.y = acc[mf][nf][3] * BINV;
            if (MODE >= 1) {
                v0.x = geluf(v0.x); v0.y = geluf(v0.y);
                v1.x = geluf(v1.x); v1.y = geluf(v1.y);
            }
            if (MODE == 2) {
                size_t o0 = (size_t)row0 * Ncols + col;
                size_t o1 = (size_t)(row0 + 8) * Ncols + col;
                __half2 h0 = __floats2half2_rn(v0.x, v0.y);
                float2 f0 = __half22float2(h0);
                __half2 l0 = __floats2half2_rn(v0.x - f0.x, v0.y - f0.y);
                __half2 h1 = __floats2half2_rn(v1.x, v1.y);
                float2 f1 = __half22float2(h1);
                __half2 l1 = __floats2half2_rn(v1.x - f1.x, v1.y - f1.y);
                *(__half2*)(CHi + o0) = h0; *(__half2*)(CLo + o0) = l0;
                *(__half2*)(CHi + o1) = h1; *(__half2*)(CLo + o1) = l1;
            } else {
                *(float2*)(Cf + (size_t)row0 * Ncols + col) = v0;
                *(float2*)(Cf + (size_t)(row0 + 8) * Ncols + col) = v1;
            }
        }
    }
}

// ---------------- fused prep: x partial-max + x hi/lo planes + ip hi/lo planes ----------------
__global__ void k_prep(const float* __restrict__ x, const float* __restrict__ ip) {
    int tid = threadIdx.x;
    if (blockIdx.x < 128) {
        int b = blockIdx.x >> 4, sc = blockIdx.x & 15;
        int s0 = sc * 128;
        #pragma unroll
        for (int dg = 0; dg < 4; dg++) {
            int d = dg * 256 + tid;
            size_t base = ((size_t)(b * SS + s0)) * DM + d;
            const float* px = x + base;
            __half* ph = g_xHi + base;
            __half* pl = g_xLo + base;
            float m = -INFINITY;
            #pragma unroll 4
            for (int s = 0; s < 128; s++) {
                float v = px[(size_t)s * DM];
                m = fmaxf(m, v);
                __half h = __float2half_rn(v);
                ph[(size_t)s * DM] = h;
                pl[(size_t)s * DM] = __float2half_rn(v - __half2float(h));
            }
            g_pmax[(sc * BB + b) * DM + d] = m;
        }
    } else {
        size_t t = (size_t)(blockIdx.x - 128) * 256 + tid;
        float4 v = ((const float4*)ip)[t];
        v.x *= BSCALE; v.y *= BSCALE; v.z *= BSCALE; v.w *= BSCALE;
        __half2 h0 = __floats2half2_rn(v.x, v.y), h1 = __floats2half2_rn(v.z, v.w);
        float2 f0 = __half22float2(h0), f1 = __half22float2(h1);
        __half2 l0 = __floats2half2_rn(v.x - f0.x, v.y - f0.y);
        __half2 l1 = __floats2half2_rn(v.z - f1.x, v.w - f1.y);
        ((__half2*)g_ipHi)[2 * t] = h0; ((__half2*)g_ipHi)[2 * t + 1] = h1;
        ((__half2*)g_ipLo)[2 * t] = l0; ((__half2*)g_ipLo)[2 * t + 1] = l1;
    }
}

// ---------------- router: pmax reduce -> mlp1 -> gelu -> LN -> mlp2 -> logits ----------------
__global__ void __launch_bounds__(512) k_router(
    const float* __restrict__ W1, const float* __restrict__ b1,
    const float* __restrict__ lng, const float* __restrict__ lnb,
    const float* __restrict__ W2, const float* __restrict__ b2,
    const float* __restrict__ nk)
{
    int b = blockIdx.x, tid = threadIdx.x, wid = tid >> 5, lane = tid & 31;
    __shared__ float sg[1024];
    __shared__ float sh[512];
    __shared__ float red[512];
    __shared__ float sq[256];
    for (int d = tid; d < 1024; d += 512) {
        float m = -INFINITY;
        #pragma unroll
        for (int sc = 0; sc < 16; sc++) m = fmaxf(m, g_pmax[(sc * BB + b) * DM + d]);
        sg[d] = m;
    }
    __syncthreads();
    for (int oo = 0; oo < 32; oo++) {
        int o = wid * 32 + oo;
        const float* w = W1 + (size_t)o * 1024;
        float s = 0.f;
        for (int k = lane; k < 1024; k += 32) s += sg[k] * w[k];
        #pragma unroll
        for (int off = 16; off; off >>= 1) s += __shfl_xor_sync(0xffffffffu, s, off);
        if (lane == 0) sh[o] = geluf(s + b1[o]);
    }
    __syncthreads();
    float v = sh[tid];
    red[tid] = v;
    for (int s = 256; s; s >>= 1) { __syncthreads(); if (tid < s) red[tid] += red[tid + s]; }
    __syncthreads();
    float mu = red[0] * (1.f / 512.f);
    __syncthreads();
    float dv = v - mu;
    red[tid] = dv * dv;
    for (int s = 256; s; s >>= 1) { __syncthreads(); if (tid < s) red[tid] += red[tid + s]; }
    __syncthreads();
    float var = red[0] * (1.f / 512.f);
    __syncthreads();
    sh[tid] = dv * rsqrtf(var + 1e-5f) * lng[tid] + lnb[tid];
    __syncthreads();
    for (int oo = 0; oo < 16; oo++) {
        int o = wid * 16 + oo;
        const float* w = W2 + (size_t)o * 512;
        float s = 0.f;
        for (int k = lane; k < 512; k += 32) s += sh[k] * w[k];
        #pragma unroll
        for (int off = 16; off; off >>= 1) s += __shfl_xor_sync(0xffffffffu, s, off);
        if (lane == 0) sq[o] = s + b2[o];
    }
    __syncthreads();
    for (int oo = 0; oo < 256; oo++) {
        int n = wid * 256 + oo;
        const float* w = nk + (size_t)n * 256;
        float s = 0.f;
        #pragma unroll
        for (int k = lane; k < 256; k += 32) s += sq[k] * w[k];
        #pragma unroll
        for (int off = 16; off; off >>= 1) s += __shfl_xor_sync(0xffffffffu, s, off);
        if (lane == 0) g_logits[b * 4096 + n] = s * 0.0625f;
    }
}

// ---------------- exact top-k via bitonic sort; index set emitted sorted ascending ----------------
__global__ void k_topk(const float* __restrict__ vals, int N, int Ksel, int* __restrict__ outIdx) {
    __shared__ float sv[4096];
    __shared__ int   si[4096];
    int b = blockIdx.x, tid = threadIdx.x, bs = blockDim.x;
    for (int i = tid; i < N; i += bs) { sv[i] = vals[b * N + i]; si[i] = i; }
    for (int k = 2; k <= N; k <<= 1) {
        for (int j = k >> 1; j > 0; j >>= 1) {
            __syncthreads();
            for (int i = tid; i < N; i += bs) {
                int l = i ^ j;
                if (l > i) {
                    float vi = sv[i], vl = sv[l];
                    int ii = si[i], il = si[l];
                    bool lFirst = (vl > vi) || (vl == vi && il < ii);
                    bool sw = ((i & k) == 0) ? lFirst : !lFirst;
                    if (sw) { sv[i] = vl; sv[l] = vi; si[i] = il; si[l] = ii; }
                }
            }
        }
    }
    __syncthreads();
    int* sel = (int*)sv;
    for (int i = tid; i < Ksel; i += bs) sel[i] = si[i];
    for (int k = 2; k <= Ksel; k <<= 1) {
        for (int j = k >> 1; j > 0; j >>= 1) {
            __syncthreads();
            for (int i = tid; i < Ksel; i += bs) {
                int l = i ^ j;
                if (l > i) {
                    int a = sel[i], c = sel[l];
                    bool sw = ((i & k) == 0) ? (c < a) : (c > a);
                    if (sw) { sel[i] = c; sel[l] = a; }
                }
            }
        }
    }
    __syncthreads();
    for (int i = tid; i < Ksel; i += bs) outIdx[b * Ksel + i] = sel[i];
}

// ---------------- gathers / reductions (emit half hi/lo planes) ----------------
__global__ void k_gather_wsel(const float* __restrict__ pw) {
    size_t t = (size_t)blockIdx.x * blockDim.x + threadIdx.x;
    int j = (int)(t & (KI - 1));
    size_t bp = t >> 11;
    int p = (int)(bp & (NP - 1));
    int b = (int)(bp >> 11);
    float v = pw[(size_t)p * NIN + g_iidx[b * KI + j]] * BSCALE;
    __half h = __float2half_rn(v);
    g_wselHi[t] = h;
    g_wselLo[t] = __float2half_rn(v - __half2float(h));
}

__global__ void k_scores() {
    int t = blockIdx.x * blockDim.x + threadIdx.x;
    int b = t >> 11, p = t & (NP - 1);
    const float* q = g_pa + (size_t)b * SS * NP + p;
    float s = 0.f;
    #pragma unroll 4
    for (int i = 0; i < SS; i++) s += q[(size_t)i * NP];
    g_scores[t] = s * (1.f / (float)SS);
}

__global__ void k_gather_pasel() {
    size_t t = (size_t)blockIdx.x * blockDim.x + threadIdx.x;
    int q = (int)(t & (KP - 1));
    size_t bs_ = t >> 10;
    int s = (int)(bs_ & (SS - 1));
    int b = (int)(bs_ >> 11);
    float v = g_pa[((size_t)(b * SS + s)) * NP + g_pidx[b * KP + q]];
    __half h = __float2half_rn(v);
    g_paselHi[t] = h;
    g_paselLo[t] = __float2half_rn(v - __half2float(h));
}

// poT[b][d][q] = po[pidx[b][q]][d] * BSCALE, as hi/lo planes (32x32 smem transpose)
__global__ void k_build_poT(const float* __restrict__ po) {
    __shared__ float t[32][33];
    int b = blockIdx.z;
    int q0 = blockIdx.x * 32, d0 = blockIdx.y * 32;
    int tx = threadIdx.x, ty = threadIdx.y;
    for (int yy = ty; yy < 32; yy += 8) {
        int p = g_pidx[b * KP + q0 + yy];
        t[yy][tx] = po[(size_t)p * DM + d0 + tx];
    }
    __syncthreads();
    for (int yy = ty; yy < 32; yy += 8) {
        float v = t[tx][yy] * BSCALE;
        size_t idx = ((size_t)b * DM + d0 + yy) * KP + q0 + tx;
        __half h = __float2half_rn(v);
        g_poTHi[idx] = h;
        g_poTLo[idx] = __float2half_rn(v - __half2float(h));
    }
}

// ---------------- launch ----------------
extern "C" void kernel_launch(void* const* d_in, const int* in_sizes, int n_in,
                              void* d_out, int out_size) {
    const float* x   = (const float*)d_in[0];
    const float* W1  = (const float*)d_in[3];
    const float* b1  = (const float*)d_in[4];
    const float* lng = (const float*)d_in[5];
    const float* lnb = (const float*)d_in[6];
    const float* W2  = (const float*)d_in[7];
    const float* b2  = (const float*)d_in[8];
    const float* nk  = (const float*)d_in[9];
    const float* ip  = (const float*)d_in[10];
    const float* pw  = (const float*)d_in[11];
    const float* po  = (const float*)d_in[12];
    float* out = (float*)d_out;

    float *p_logits, *p_scores, *p_pa;
    int *p_iidx, *p_pidx;
    __half *p_xHi, *p_xLo, *p_ipHi, *p_ipLo, *p_selinHi, *p_selinLo;
    __half *p_wselHi, *p_wselLo, *p_paselHi, *p_paselLo, *p_poTHi, *p_poTLo;
    cudaGetSymbolAddress((void**)&p_logits, g_logits);
    cudaGetSymbolAddress((void**)&p_scores, g_scores);
    cudaGetSymbolAddress((void**)&p_pa,     g_pa);
    cudaGetSymbolAddress((void**)&p_iidx,   g_iidx);
    cudaGetSymbolAddress((void**)&p_pidx,   g_pidx);
    cudaGetSymbolAddress((void**)&p_xHi,    g_xHi);
    cudaGetSymbolAddress((void**)&p_xLo,    g_xLo);
    cudaGetSymbolAddress((void**)&p_ipHi,   g_ipHi);
    cudaGetSymbolAddress((void**)&p_ipLo,   g_ipLo);
    cudaGetSymbolAddress((void**)&p_selinHi, g_selinHi);
    cudaGetSymbolAddress((void**)&p_selinLo, g_selinLo);
    cudaGetSymbolAddress((void**)&p_wselHi, g_wselHi);
    cudaGetSymbolAddress((void**)&p_wselLo, g_wselLo);
    cudaGetSymbolAddress((void**)&p_paselHi, g_paselHi);
    cudaGetSymbolAddress((void**)&p_paselLo, g_paselLo);
    cudaGetSymbolAddress((void**)&p_poTHi,  g_poTHi);
    cudaGetSymbolAddress((void**)&p_poTLo,  g_poTLo);

    cudaFuncSetAttribute(mma_nt_h<2, true >, cudaFuncAttributeMaxDynamicSharedMemorySize, SMEM_BYTES);
    cudaFuncSetAttribute(mma_nt_h<1, false>, cudaFuncAttributeMaxDynamicSharedMemorySize, SMEM_BYTES);
    cudaFuncSetAttribute(mma_nt_h<0, false>, cudaFuncAttributeMaxDynamicSharedMemorySize, SMEM_BYTES);

    // 0: fused prep (x partial-max + x planes + ip planes)
    k_prep<<<128 + (int)((size_t)NIN * DM / 4 / 256), 256>>>(x, ip);
    // 1: router
    k_router<<<BB, 512>>>(W1, b1, lng, lnb, W2, b2, nk);
    // 2: input top-k
    k_topk<<<BB, 1024>>>(p_logits, NIN, KI, p_iidx);

    // 3: gemm1 (profiled slot): selin(planes) = gelu(x @ gathered_patterns^T)
    mma_nt_h<2, true><<<dim3(KI / 128, SS / 256, BB), 512, SMEM_BYTES>>>(
        p_xHi, p_xLo, p_ipHi, p_ipLo, nullptr, p_selinHi, p_selinLo,
        p_iidx, KI, DM, (size_t)SS * DM, 0, (size_t)SS * KI, KI);

    // 4: gather pw columns -> wsel planes
    k_gather_wsel<<<(int)((size_t)BB * NP * KI / 256), 256>>>(pw);

    // 5: gemm2: pa(fp32) = gelu(selin @ wsel^T)
    mma_nt_h<1, false><<<dim3(NP / 128, SS / 256, BB), 512, SMEM_BYTES>>>(
        p_selinHi, p_selinLo, p_wselHi, p_wselLo, p_pa, nullptr, nullptr,
        nullptr, NP, KI, (size_t)SS * KI, (size_t)NP * KI, (size_t)SS * NP, 0);

    // 6-9: process selection + operand prep
    k_scores<<<BB * NP / 256, 256>>>();
    k_topk<<<BB, 1024>>>(p_scores, NP, KP, p_pidx);
    k_gather_pasel<<<(int)((size_t)BB * SS * KP / 256), 256>>>();
    k_build_poT<<<dim3(KP / 32, DM / 32, BB), dim3(32, 8)>>>(po);

    // 10: gemm3: out(fp32) = pasel @ poT^T
    mma_nt_h<0, false><<<dim3(DM / 128, SS / 256, BB), 512, SMEM_BYTES>>>(
        p_paselHi, p_paselLo, p_poTHi, p_poTLo, out, nullptr, nullptr,
        nullptr, DM, KP, (size_t)SS * KP, (size_t)DM * KP, (size_t)SS * DM, 0);
}